// round 14
// baseline (speedup 1.0000x reference)
#include <cuda_runtime.h>
#include <cuda_bf16.h>
#include <math.h>

typedef unsigned int uint;
typedef __nv_bfloat16 bf16;

#define VOCAB 32000
#define HDIM  1024
#define EHDIM 1024
#define NB    32
#define LSEQ  128
#define XDIM  2048
#define G3H   3072
#define NROW  (NB*LSEQ)
#define NBH   (NB*HDIM)
#define NBG   (NB*G3H)

#define AROW  136
#define CHA   (32*AROW)
#define CHW   (64*AROW)
#define MSTAGE_B ((CHA+CHW)*2)     // 26112 bytes per stage
#define NSTG  3
#define MBAR_OFF  (NSTG*MSTAGE_B)
#define SMEM_MEGA (NSTG*MSTAGE_B + 64)

#define FROW  72
#define FSTAGE_B (256*144)
#define SMEM_FC  (2*FSTAGE_B + 16)
#define FBAR_OFF (2*FSTAGE_B)

#define UBUF 3456

// ---------------- scratch ----------------
__device__ __align__(256) float g_Uk[NB*LSEQ*HDIM];
__device__ __align__(256) float g_h0f[NBH];
__device__ __align__(256) float g_h1f[NBH];
__device__ __align__(256) bf16  g_qb[16*CHA];
__device__ __align__(256) bf16  g_h0b[8*CHA];
__device__ __align__(256) bf16  g_xb[16*CHA];
__device__ __align__(256) float g_Wq[NBH];
__device__ __align__(256) float g_scores[NB*LSEQ];
__device__ __align__(256) float g_gh0[NBG];
__device__ __align__(256) float g_gh1[NBG];
__device__ __align__(256) float g_gi0[NBG];
__device__ __align__(256) float g_gi1[NBG];
__device__ __align__(256) bf16  g_wWa[16*16*CHW];
__device__ __align__(256) bf16  g_wHh0[48*8*CHW];
__device__ __align__(256) bf16  g_wHh1[48*8*CHW];
__device__ __align__(256) bf16  g_wIh0[48*16*CHW];
__device__ __align__(256) bf16  g_wIh1[48*8*CHW];
__device__ __align__(256) bf16  g_fcwt[(size_t)16*VOCAB*FROW];
__device__ __align__(256) bf16  g_A2t[(size_t)16*NROW*FROW];
__device__ unsigned g_bar;
__device__ unsigned g_gen;

// ---------------- helpers ----------------
__device__ __forceinline__ float tanha(float x) {
    float r; asm("tanh.approx.f32 %0,%1;" : "=f"(r) : "f"(x)); return r;
}
__device__ __forceinline__ float sigp(float x) { return 1.f / (1.f + __expf(-x)); }
__device__ __forceinline__ float wsum(float v) {
#pragma unroll
    for (int o = 16; o > 0; o >>= 1) v += __shfl_xor_sync(0xffffffffu, v, o);
    return v;
}
__device__ __forceinline__ float wmaxr(float v) {
#pragma unroll
    for (int o = 16; o > 0; o >>= 1) v = fmaxf(v, __shfl_xor_sync(0xffffffffu, v, o));
    return v;
}

__device__ __forceinline__ void mbar_init(uint a, uint cnt) {
    asm volatile("mbarrier.init.shared::cta.b64 [%0], %1;" :: "r"(a), "r"(cnt));
}
__device__ __forceinline__ void mbar_expect(uint a, uint tx) {
    asm volatile("mbarrier.arrive.expect_tx.shared::cta.b64 _, [%0], %1;"
                 :: "r"(a), "r"(tx) : "memory");
}
__device__ __forceinline__ void bulk_g2s(uint dst, const void* src, uint bytes, uint mbar) {
    asm volatile("cp.async.bulk.shared::cta.global.mbarrier::complete_tx::bytes "
                 "[%0], [%1], %2, [%3];"
                 :: "r"(dst), "l"(src), "r"(bytes), "r"(mbar) : "memory");
}
__device__ __forceinline__ void mbar_wait(uint a, uint par) {
    asm volatile("{\n\t.reg .pred P;\nWAITL_%=:\n\t"
                 "mbarrier.try_wait.parity.shared::cta.b64 P, [%0], %1, 0x989680;\n\t"
                 "@P bra DONEL_%=;\n\tbra WAITL_%=;\nDONEL_%=:\n\t}"
                 :: "r"(a), "r"(par) : "memory");
}
__device__ __forceinline__ void fence_proxy() {
    asm volatile("fence.proxy.async.shared::cta;" ::: "memory");
}
__device__ __forceinline__ void cpa16(uint dst, const void* src) {
    asm volatile("cp.async.cg.shared.global [%0], [%1], 16;\n" :: "r"(dst), "l"(src));
}
#define CP_COMMIT asm volatile("cp.async.commit_group;\n")
#define CP_WAIT1  asm volatile("cp.async.wait_group 1;\n" ::: "memory")
#define CP_WAIT0  asm volatile("cp.async.wait_group 0;\n" ::: "memory")

__device__ __forceinline__ void mma_bf16(float* c, uint a0, uint a1, uint a2, uint a3,
                                         uint b0, uint b1) {
    asm volatile(
        "mma.sync.aligned.m16n8k16.row.col.f32.bf16.bf16.f32 "
        "{%0,%1,%2,%3}, {%4,%5,%6,%7}, {%8,%9}, {%0,%1,%2,%3};\n"
        : "+f"(c[0]), "+f"(c[1]), "+f"(c[2]), "+f"(c[3])
        : "r"(a0), "r"(a1), "r"(a2), "r"(a3), "r"(b0), "r"(b1));
}
__device__ __forceinline__ void mma_tf32(float* c, float a0, float a1, float a2, float a3,
                                         float b0, float b1) {
    asm volatile(
        "mma.sync.aligned.m16n8k8.row.col.f32.tf32.tf32.f32 "
        "{%0,%1,%2,%3},{%4,%5,%6,%7},{%8,%9},{%0,%1,%2,%3};\n"
        : "+f"(c[0]), "+f"(c[1]), "+f"(c[2]), "+f"(c[3])
        : "r"(__float_as_uint(a0)), "r"(__float_as_uint(a1)),
          "r"(__float_as_uint(a2)), "r"(__float_as_uint(a3)),
          "r"(__float_as_uint(b0)), "r"(__float_as_uint(b1)));
}

// ---------------- grid barrier ----------------
__device__ __forceinline__ void gsync(int nb) {
    __syncthreads();
    if (threadIdx.x == 0) {
        volatile unsigned* vg = &g_gen;
        unsigned gen = *vg;
        __threadfence();
        unsigned old = atomicInc(&g_bar, (unsigned)(nb - 1));
        if (old == (unsigned)(nb - 1)) {
            __threadfence();
            *vg = gen + 1;
        } else {
            while (*vg == gen) { }
            __threadfence();
        }
    }
    __syncthreads();
}

// ---------------- bf16 mma task: C[32][64@jbase] += A(4 chunks) @ W^T (atomicAdd) ------
// 4 warpN x 2 k-halves; each warp computes 32x16 over half the k-range.
// B fragments read by exactly one warp (crossbar -25% vs 2x4 tiling).
__device__ void gemm_bf(const bf16* __restrict__ A, const bf16* __restrict__ W,
                        float* __restrict__ C, int ldc, int jbase,
                        char* sm, int* par) {
    const int tid = threadIdx.x;
    const int lane = tid & 31, wid = tid >> 5;
    const int warpN = wid & 3, kh = wid >> 2;
    const int g = lane >> 2, tg = lane & 3;
    const int n0 = warpN * 16;
    uint sb = (uint)__cvta_generic_to_shared(sm);
    uint mb = sb + MBAR_OFF;

    float acc[2][2][4];   // [mtile][nhalf][4]
#pragma unroll
    for (int m = 0; m < 2; m++)
#pragma unroll
        for (int h = 0; h < 2; h++)
#pragma unroll
            for (int u = 0; u < 4; u++) acc[m][h][u] = 0.f;

#define MISSUE(c) do { \
    int _s = (c) % NSTG; uint _mbar = mb + _s * 8; \
    if (tid == 0) { \
        mbar_expect(_mbar, MSTAGE_B); \
        uint _dst = sb + _s * MSTAGE_B; \
        bulk_g2s(_dst, A + (c) * CHA, CHA * 2, _mbar); \
        bulk_g2s(_dst + CHA * 2, W + (size_t)(c) * CHW, CHW * 2, _mbar); \
    } } while (0)

    MISSUE(0);
    MISSUE(1);
    for (int c = 0; c < 4; ++c) {
        if (c + 2 < 4) MISSUE(c + 2);
        int s = c % NSTG;
        mbar_wait(mb + s * 8, (uint)par[s]);
        par[s] ^= 1;
        const bf16* bA = (const bf16*)(sm + s * MSTAGE_B);
        const bf16* bW = bA + CHA;
#pragma unroll
        for (int ks = 0; ks < 4; ks++) {
            int k0 = (kh * 4 + ks) * 16 + tg * 2;
            uint a00 = *(const uint*)&bA[(g)      * AROW + k0];
            uint a01 = *(const uint*)&bA[(g + 8)  * AROW + k0];
            uint a02 = *(const uint*)&bA[(g)      * AROW + k0 + 8];
            uint a03 = *(const uint*)&bA[(g + 8)  * AROW + k0 + 8];
            uint a10 = *(const uint*)&bA[(g + 16) * AROW + k0];
            uint a11 = *(const uint*)&bA[(g + 24) * AROW + k0];
            uint a12 = *(const uint*)&bA[(g + 16) * AROW + k0 + 8];
            uint a13 = *(const uint*)&bA[(g + 24) * AROW + k0 + 8];
            uint b00 = *(const uint*)&bW[(n0 + g)     * AROW + k0];
            uint b01 = *(const uint*)&bW[(n0 + g)     * AROW + k0 + 8];
            uint b10 = *(const uint*)&bW[(n0 + 8 + g) * AROW + k0];
            uint b11 = *(const uint*)&bW[(n0 + 8 + g) * AROW + k0 + 8];
            mma_bf16(acc[0][0], a00, a01, a02, a03, b00, b01);
            mma_bf16(acc[0][1], a00, a01, a02, a03, b10, b11);
            mma_bf16(acc[1][0], a10, a11, a12, a13, b00, b01);
            mma_bf16(acc[1][1], a10, a11, a12, a13, b10, b11);
        }
        __syncthreads();
    }
#undef MISSUE

#pragma unroll
    for (int m = 0; m < 2; m++) {
        int mr = m * 16 + g;
#pragma unroll
        for (int h = 0; h < 2; h++) {
            int j = jbase + n0 + h * 8 + tg * 2;
            atomicAdd(&C[(size_t)mr * ldc + j],           acc[m][h][0]);
            atomicAdd(&C[(size_t)mr * ldc + j + 1],       acc[m][h][1]);
            atomicAdd(&C[(size_t)(mr + 8) * ldc + j],     acc[m][h][2]);
            atomicAdd(&C[(size_t)(mr + 8) * ldc + j + 1], acc[m][h][3]);
        }
    }
}

__device__ __forceinline__ void preset3h(float* dst, const float* bias, int n) {
    float* p = dst + (size_t)n * G3H;
    for (int j = threadIdx.x; j < G3H; j += 256) p[j] = bias[j];
}
__device__ __forceinline__ void preset1h(float* dst, const float* bias, int n) {
    float* p = dst + (size_t)n * HDIM;
    for (int j = threadIdx.x; j < HDIM; j += 256) p[j] = bias[j];
}

// ---------------- persistent megakernel (2 blocks/SM) ----------------
__global__ void __launch_bounds__(256, 2) k_mega(
    const float* __restrict__ enc, const int* __restrict__ tgt,
    const float* __restrict__ emb,
    const float* __restrict__ Wa_b,
    const float* __restrict__ Va_w, const float* __restrict__ Va_b,
    const float* __restrict__ bih0, const float* __restrict__ bhh0,
    const float* __restrict__ bih1, const float* __restrict__ bhh1,
    const float* __restrict__ fcw,
    float* __restrict__ att) {
    extern __shared__ char dynsm[];
    const int nbk = gridDim.x;
    const int tid = threadIdx.x;
    const int wid = tid >> 5, lane = tid & 31;
    const int gw = blockIdx.x * 8 + wid;
    const int NW = nbk * 8;
    const int gt = blockIdx.x * 256 + tid;
    const int NT = nbk * 256;
    const float Vab = Va_b[0];
    int par[NSTG];
#pragma unroll
    for (int s = 0; s < NSTG; s++) par[s] = 0;

    {
        uint mb = (uint)__cvta_generic_to_shared(dynsm) + MBAR_OFF;
        if (tid == 0)
            for (int s = 0; s < NSTG; s++) mbar_init(mb + s * 8, 1);
        fence_proxy();
    }
    __syncthreads();

    for (int step = 0; step < LSEQ; step++) {
        // ---- P1: Wq x4 (64) + gh0 x2 (96) + gh1 x2 (96) + preset gi1 (32)
        for (int t = blockIdx.x; t < 288; t += nbk) {
            if (t < 64) {
                int p = t >> 4, jt = t & 15;
                gemm_bf(g_qb + p * 4 * CHA, g_wWa + (size_t)(jt * 16 + p * 4) * CHW,
                        g_Wq, HDIM, jt * 64, dynsm, par);
            } else if (t < 160) {
                int u = t - 64, p = u / 48, jt = u % 48;
                gemm_bf(g_qb + p * 4 * CHA, g_wHh0 + (size_t)(jt * 8 + p * 4) * CHW,
                        g_gh0, G3H, jt * 64, dynsm, par);
            } else if (t < 256) {
                int u = t - 160, p = u / 48, jt = u % 48;
                gemm_bf(g_qb + (8 + p * 4) * CHA, g_wHh1 + (size_t)(jt * 8 + p * 4) * CHW,
                        g_gh1, G3H, jt * 64, dynsm, par);
            } else {
                preset3h(g_gi1, bih1, t - 256);
            }
        }
        gsync(nbk);

        // ---- P2a: scores (MUFU tanh.approx)
        for (int t = gw; t < NB * LSEQ; t += NW) {
            int n = t >> 7;
            const float4* uk = (const float4*)(g_Uk + (size_t)t * HDIM);
            const float4* wq = (const float4*)(g_Wq + n * HDIM);
            const float4* va = (const float4*)Va_w;
            float s = 0.f;
#pragma unroll 2
            for (int i = lane; i < 256; i += 32) {
                float4 u = uk[i], q = wq[i], v = va[i];
                s += v.x * tanha(u.x + q.x);
                s += v.y * tanha(u.y + q.y);
                s += v.z * tanha(u.z + q.z);
                s += v.w * tanha(u.w + q.w);
            }
            s = wsum(s);
            if (lane == 0) g_scores[t] = s + Vab;
        }
        gsync(nbk);

        // ---- P2c: softmax + context + embedding -> g_xb (chunk-major), att out
        for (int t = gw; t < 2048; t += NW) {
            if (t < 1024) {
                int n = t >> 5, c = t & 31, d = c * 32 + lane;
                const float* sc = g_scores + n * LSEQ;
                float e[4];
                float m0 = fmaxf(fmaxf(sc[lane * 4 + 0], sc[lane * 4 + 1]),
                                 fmaxf(sc[lane * 4 + 2], sc[lane * 4 + 3]));
                float mx = wmaxr(m0);
                float lsum = 0.f;
#pragma unroll
                for (int i = 0; i < 4; i++) { e[i] = __expf(sc[lane * 4 + i] - mx); lsum += e[i]; }
                float inv = __fdividef(1.f, wsum(lsum));
                if (c == 0) {
                    float* ap = att + ((size_t)n * LSEQ + step) * LSEQ + lane * 4;
#pragma unroll
                    for (int i = 0; i < 4; i++) ap[i] = e[i] * inv;
                }
                float ctx0 = 0.f, ctx1 = 0.f;
                const float* ep = enc + (size_t)n * EHDIM + d;
#pragma unroll 4
                for (int l = 0; l < LSEQ; l += 2) {
                    float w0 = __shfl_sync(0xffffffffu, e[l & 3], l >> 2);
                    float w1 = __shfl_sync(0xffffffffu, e[(l + 1) & 3], (l + 1) >> 2);
                    ctx0 += w0 * ep[(size_t)l * (NB * EHDIM)];
                    ctx1 += w1 * ep[(size_t)(l + 1) * (NB * EHDIM)];
                }
                g_xb[(d >> 7) * CHA + n * AROW + (d & 127)] =
                    __float2bfloat16((ctx0 + ctx1) * inv);
            } else {
                int u = t - 1024;
                int n = u >> 5, c = u & 31, j = c * 32 + lane;
                int tok = tgt[n * LSEQ + step];
                g_xb[(8 + (j >> 7)) * CHA + n * AROW + (j & 127)] =
                    __float2bfloat16(emb[(size_t)tok * HDIM + j]);
            }
        }
        gsync(nbk);

        // ---- P3: gi0 x4 (192) + preset Wq (32)
        for (int t = blockIdx.x; t < 224; t += nbk) {
            if (t < 192) {
                int p = t / 48, jt = t % 48;
                gemm_bf(g_xb + p * 4 * CHA, g_wIh0 + (size_t)(jt * 16 + p * 4) * CHW,
                        g_gi0, G3H, jt * 64, dynsm, par);
            } else {
                preset1h(g_Wq, Wa_b, t - 192);
            }
        }
        gsync(nbk);

        // ---- comb0 -> h0; preset gh0 in place
        for (int i = gt; i < NBH; i += NT) {
            int n = i >> 10, j = i & 1023;
            int b = n * G3H + j;
            float r = sigp(g_gi0[b] + g_gh0[b]);
            float z = sigp(g_gi0[b + HDIM] + g_gh0[b + HDIM]);
            float nn = tanhf(g_gi0[b + 2 * HDIM] + r * g_gh0[b + 2 * HDIM]);
            float h = (1.f - z) * nn + z * g_h0f[i];
            g_h0f[i] = h;
            bf16 hb = __float2bfloat16(h);
            int ca = (j >> 7) * CHA + n * AROW + (j & 127);
            g_h0b[ca] = hb;
            g_qb[ca] = hb;
            g_gh0[b] = bhh0[j];
            g_gh0[b + HDIM] = bhh0[j + HDIM];
            g_gh0[b + 2 * HDIM] = bhh0[j + 2 * HDIM];
        }
        gsync(nbk);

        // ---- P4: gi1 x2 (96) + preset gi0 (32) + fcw->fcwt conversion on idle blocks
        for (int t = blockIdx.x; t < 304; t += nbk) {
            if (t < 96) {
                int p = t / 48, jt = t % 48;
                gemm_bf(g_h0b + p * 4 * CHA, g_wIh1 + (size_t)(jt * 8 + p * 4) * CHW,
                        g_gi1, G3H, jt * 64, dynsm, par);
            } else if (t < 128) {
                preset3h(g_gi0, bih0, t - 96);
            } else {
                long base = ((long)step * 176 + (t - 128)) * 1536;
#pragma unroll
                for (int u = 0; u < 6; u++) {
                    long i = base + u * 256 + tid;
                    if (i < (long)VOCAB * HDIM) {
                        int v = (int)(i >> 10), k = (int)(i & 1023);
                        g_fcwt[((size_t)(k >> 6) * VOCAB + v) * FROW + (k & 63)] =
                            __float2bfloat16(fcw[i]);
                    }
                }
            }
        }
        gsync(nbk);

        // ---- comb1 -> h1, A2t; preset gh1 in place
        for (int i = gt; i < NBH; i += NT) {
            int n = i >> 10, j = i & 1023;
            int b = n * G3H + j;
            float r = sigp(g_gi1[b] + g_gh1[b]);
            float z = sigp(g_gi1[b + HDIM] + g_gh1[b + HDIM]);
            float nn = tanhf(g_gi1[b + 2 * HDIM] + r * g_gh1[b + 2 * HDIM]);
            float h = (1.f - z) * nn + z * g_h1f[i];
            g_h1f[i] = h;
            bf16 hb = __float2bfloat16(h);
            g_qb[(8 + (j >> 7)) * CHA + n * AROW + (j & 127)] = hb;
            g_A2t[((size_t)(j >> 6) * NROW + step * NB + n) * FROW + (j & 63)] = hb;
            g_gh1[b] = bhh1[j];
            g_gh1[b + HDIM] = bhh1[j + HDIM];
            g_gh1[b + 2 * HDIM] = bhh1[j + 2 * HDIM];
        }
        gsync(nbk);
    }
}

// ---------------- init ----------------
__global__ void k_init(const float* __restrict__ Wa_b,
                       const float* __restrict__ bhh0, const float* __restrict__ bhh1,
                       const float* __restrict__ bih0, const float* __restrict__ bih1) {
    int i0 = blockIdx.x * 256 + threadIdx.x;
    int st = gridDim.x * 256;
    if (i0 == 0) { g_bar = 0; g_gen = 0; }
    bf16 z = __float2bfloat16(0.f);
    for (int i = i0; i < NBH; i += st) {
        g_h0f[i] = 0.f; g_h1f[i] = 0.f;
        g_Wq[i] = Wa_b[i & 1023];
    }
    for (int i = i0; i < 16 * CHA; i += st) g_qb[i] = z;
    for (int i = i0; i < 8 * CHA; i += st) g_h0b[i] = z;
    for (int i = i0; i < NBG; i += st) {
        int j = i % G3H;
        g_gh0[i] = bhh0[j]; g_gh1[i] = bhh1[j];
        g_gi0[i] = bih0[j]; g_gi1[i] = bih1[j];
    }
}

// ---------------- weight conversion (recurrent weights only; fcw done in k_mega) ------
__global__ void k_cvtw(const float* __restrict__ wa, const float* __restrict__ hh0,
                       const float* __restrict__ hh1, const float* __restrict__ ih0,
                       const float* __restrict__ ih1) {
    long st = (long)gridDim.x * blockDim.x;
    long i0 = (long)blockIdx.x * blockDim.x + threadIdx.x;
    for (long i = i0; i < (long)HDIM * XDIM; i += st) {
        int j = (int)(i >> 11), k = (int)(i & 2047);
        g_wWa[(size_t)((j >> 6) * 16 + (k >> 7)) * CHW + (j & 63) * AROW + (k & 127)] =
            __float2bfloat16(wa[i]);
    }
    for (long i = i0; i < (long)G3H * HDIM; i += st) {
        int j = (int)(i >> 10), k = (int)(i & 1023);
        size_t o = (size_t)((j >> 6) * 8 + (k >> 7)) * CHW + (j & 63) * AROW + (k & 127);
        g_wHh0[o] = __float2bfloat16(hh0[i]);
        g_wHh1[o] = __float2bfloat16(hh1[i]);
        g_wIh1[o] = __float2bfloat16(ih1[i]);
    }
    for (long i = i0; i < (long)G3H * XDIM; i += st) {
        int j = (int)(i >> 11), k = (int)(i & 2047);
        g_wIh0[(size_t)((j >> 6) * 16 + (k >> 7)) * CHW + (j & 63) * AROW + (k & 127)] =
            __float2bfloat16(ih0[i]);
    }
}

// ---------------- Uk = keys @ Ua_w^T + Ua_b (tf32 mma, once) ----------------
__global__ void __launch_bounds__(256) k_uk(const float* __restrict__ enc,
                                            const float* __restrict__ Uw,
                                            const float* __restrict__ Ub) {
    __shared__ float sm[2 * UBUF];
    const int bm = blockIdx.y, bn = blockIdx.x;
    const int tid = threadIdx.x;
    const int lane = tid & 31, wid = tid >> 5;
    const int warpM = wid & 1, warpN = wid >> 1;
    const int g = lane >> 2, tg = lane & 3;
    const int am = tid >> 3, ak = (tid & 7) << 2;

    int r = bm * 32 + am;
    const float* Arow = enc + ((size_t)(r & 127) * NB + (r >> 7)) * EHDIM;

    float acc[2][4];
#pragma unroll
    for (int h = 0; h < 2; h++)
#pragma unroll
        for (int u = 0; u < 4; u++) acc[h][u] = 0.f;

    uint sb = (uint)__cvta_generic_to_shared(sm);

#define UISSUE(c) do { \
    uint _b = sb + (uint)(((c) & 1) * UBUF) * 4; \
    int _ko = (c) * 32; \
    cpa16(_b + (uint)(am * 36 + ak) * 4, Arow + _ko + ak); \
    _Pragma("unroll") \
    for (int _i = 0; _i < 2; _i++) { \
        int _idx = tid + _i * 256; \
        int _wn = _idx >> 3, _wk = (_idx & 7) << 2; \
        cpa16(_b + (uint)(32 * 36 + _wn * 36 + _wk) * 4, \
              Uw + (size_t)(bn * 64 + _wn) * EHDIM + _ko + _wk); \
    } } while (0)

    UISSUE(0); CP_COMMIT;
    for (int c = 0; c < 32; ++c) {
        if (c + 1 < 32) { UISSUE(c + 1); CP_COMMIT; CP_WAIT1; }
        else { CP_WAIT0; }
        __syncthreads();
        const float* bA = sm + (c & 1) * UBUF;
        const float* bW = bA + 32 * 36;
        int ar = (warpM * 16 + g) * 36;
        int br = (warpN * 16 + g) * 36;
#pragma unroll
        for (int kk = 0; kk < 4; kk++) {
            int ko = kk * 8 + tg;
            float a0 = bA[ar + ko],       a1 = bA[ar + 288 + ko];
            float a2 = bA[ar + ko + 4],   a3 = bA[ar + 288 + ko + 4];
            float b0 = bW[br + ko],       b1 = bW[br + ko + 4];
            float b2 = bW[br + 288 + ko], b3 = bW[br + 288 + ko + 4];
            mma_tf32(acc[0], a0, a1, a2, a3, b0, b1);
            mma_tf32(acc[1], a0, a1, a2, a3, b2, b3);
        }
        __syncthreads();
    }
#undef UISSUE

    int m = bm * 32 + warpM * 16 + g;
#pragma unroll
    for (int h = 0; h < 2; h++) {
        int j = bn * 64 + warpN * 16 + h * 8 + tg * 2;
        float bb0 = Ub[j], bb1 = Ub[j + 1];
        g_Uk[(size_t)m * HDIM + j]           = acc[h][0] + bb0;
        g_Uk[(size_t)m * HDIM + j + 1]       = acc[h][1] + bb1;
        g_Uk[(size_t)(m + 8) * HDIM + j]     = acc[h][2] + bb0;
        g_Uk[(size_t)(m + 8) * HDIM + j + 1] = acc[h][3] + bb1;
    }
}

// ---------------- FC: 128x128 bf16 tiles; bm fast-varying for fcw reuse ----------------
__global__ void __launch_bounds__(256, 2) k_fc(const float* __restrict__ fcb,
                                               float* __restrict__ out) {
    extern __shared__ char dynsm[];
    int bm = blockIdx.x, bn = blockIdx.y;
    int tid = threadIdx.x, wid = tid >> 5, lane = tid & 31;
    int g = lane >> 2, tg = lane & 3;
    int warpM = wid >> 2, warpN = wid & 3;
    uint sb = (uint)__cvta_generic_to_shared(dynsm);
    uint mb = sb + FBAR_OFF;
    int ph[2] = {0, 0};

    if (tid == 0) { mbar_init(mb, 1); mbar_init(mb + 8, 1); }
    fence_proxy();
    __syncthreads();

    float acc[4][4][4];
#pragma unroll
    for (int a = 0; a < 4; a++)
#pragma unroll
        for (int b = 0; b < 4; b++)
#pragma unroll
            for (int c = 0; c < 4; c++) acc[a][b][c] = 0.f;

    const bf16* Ag = g_A2t + (size_t)bm * 128 * FROW;
    const bf16* Bg = g_fcwt + (size_t)bn * 128 * FROW;

#define FISSUE(kt) do { \
    int _s = (kt) & 1; uint _mbar = mb + _s * 8; \
    if (tid == 0) { \
        mbar_expect(_mbar, FSTAGE_B); \
        uint _dst = sb + _s * FSTAGE_B; \
        bulk_g2s(_dst, Ag + (size_t)(kt) * (NROW * FROW), 128 * 144, _mbar); \
        bulk_g2s(_dst + 128 * 144, Bg + (size_t)(kt) * ((size_t)VOCAB * FROW), 128 * 144, _mbar); \
    } } while (0)

    FISSUE(0);
    for (int kt = 0; kt < 16; kt++) {
        if (kt + 1 < 16) FISSUE(kt + 1);
        int s = kt & 1;
        mbar_wait(mb + s * 8, (uint)ph[s]);
        ph[s] ^= 1;
        const bf16* As = (const bf16*)(dynsm + s * FSTAGE_B);
        const bf16* Bs = As + 128 * FROW;
#pragma unroll
        for (int ks = 0; ks < 4; ks++) {
            int k0 = ks * 16 + tg * 2;
            uint af[4][4], bf[4][2];
#pragma unroll
            for (int mt = 0; mt < 4; mt++) {
                int mrow = warpM * 64 + mt * 16 + g;
                af[mt][0] = *(const uint*)&As[mrow * FROW + k0];
                af[mt][1] = *(const uint*)&As[(mrow + 8) * FROW + k0];
                af[mt][2] = *(const uint*)&As[mrow * FROW + k0 + 8];
                af[mt][3] = *(const uint*)&As[(mrow + 8) * FROW + k0 + 8];
            }
#pragma unroll
            for (int nt = 0; nt < 4; nt++) {
                int nrow = warpN * 32 + nt * 8 + g;
                bf[nt][0] = *(const uint*)&Bs[nrow * FROW + k0];
                bf[nt][1] = *(const uint*)&Bs[nrow * FROW + k0 + 8];
            }
#pragma unroll
            for (int mt = 0; mt < 4; mt++)
#pragma unroll
                for (int nt = 0; nt < 4; nt++)
                    mma_bf16(acc[mt][nt], af[mt][0], af[mt][1], af[mt][2], af[mt][3],
                             bf[nt][0], bf[nt][1]);
        }
        __syncthreads();
    }
#undef FISSUE

#pragma unroll
    for (int mt = 0; mt < 4; mt++) {
#pragma unroll
        for (int nt = 0; nt < 4; nt++) {
            int r0 = bm * 128 + warpM * 64 + mt * 16 + g;
            int c = bn * 128 + warpN * 32 + nt * 8 + tg * 2;
            float bv0 = fcb[c], bv1 = fcb[c + 1];
            {
                int l = r0 >> 5, n = r0 & 31;
                float* p = out + ((size_t)(n * LSEQ + l)) * VOCAB + c;
                p[0] = acc[mt][nt][0] + bv0;
                p[1] = acc[mt][nt][1] + bv1;
            }
            {
                int r1 = r0 + 8;
                int l = r1 >> 5, n = r1 & 31;
                float* p = out + ((size_t)(n * LSEQ + l)) * VOCAB + c;
                p[0] = acc[mt][nt][2] + bv0;
                p[1] = acc[mt][nt][3] + bv1;
            }
        }
    }
}

// ---------------- log_softmax ----------------
__global__ void k_logsoftmax(float* __restrict__ out) {
    __shared__ float rm[256], rs[256];
    int row = blockIdx.x;
    float* p = out + (size_t)row * VOCAB;
    int t = threadIdx.x;
    float m = -1e30f, s = 0.f;
    for (int i = t; i < VOCAB; i += 256) {
        float v = p[i];
        if (v > m) { s = s * __expf(m - v) + 1.f; m = v; }
        else s += __expf(v - m);
    }
    rm[t] = m; rs[t] = s; __syncthreads();
    for (int o = 128; o > 0; o >>= 1) {
        if (t < o) {
            float m2 = rm[t + o], s2 = rs[t + o];
            float M = fmaxf(rm[t], m2);
            rs[t] = rs[t] * __expf(rm[t] - M) + s2 * __expf(m2 - M);
            rm[t] = M;
        }
        __syncthreads();
    }
    float lse = rm[0] + logf(rs[0]);
    for (int i = t; i < VOCAB; i += 256) p[i] -= lse;
}

// ---------------- launch ----------------
extern "C" void kernel_launch(void* const* d_in, const int* in_sizes, int n_in,
                              void* d_out, int out_size) {
    (void)in_sizes; (void)n_in; (void)out_size;
    const float* enc   = (const float*)d_in[0];
    const int*   tgt   = (const int*)  d_in[1];
    const float* emb   = (const float*)d_in[2];
    const float* Wa_w  = (const float*)d_in[3];
    const float* Wa_b  = (const float*)d_in[4];
    const float* Ua_w  = (const float*)d_in[5];
    const float* Ua_b  = (const float*)d_in[6];
    const float* Va_w  = (const float*)d_in[7];
    const float* Va_b  = (const float*)d_in[8];
    const float* W_ih0 = (const float*)d_in[9];
    const float* W_hh0 = (const float*)d_in[10];
    const float* b_ih0 = (const float*)d_in[11];
    const float* b_hh0 = (const float*)d_in[12];
    const float* W_ih1 = (const float*)d_in[13];
    const float* W_hh1 = (const float*)d_in[14];
    const float* b_ih1 = (const float*)d_in[15];
    const float* b_hh1 = (const float*)d_in[16];
    const float* fc_w  = (const float*)d_in[17];
    const float* fc_b  = (const float*)d_in[18];

    float* out = (float*)d_out;
    float* att = out + (size_t)NB * LSEQ * VOCAB;

    static int grid_mega = 0;
    if (grid_mega == 0) {
        cudaFuncSetAttribute(k_mega, cudaFuncAttributeMaxDynamicSharedMemorySize, SMEM_MEGA);
        cudaFuncSetAttribute(k_fc,   cudaFuncAttributeMaxDynamicSharedMemorySize, SMEM_FC);
        int dev = 0;
        cudaGetDevice(&dev);
        cudaDeviceProp prop;
        cudaGetDeviceProperties(&prop, dev);
        int perSM = 1;
        cudaOccupancyMaxActiveBlocksPerMultiprocessor(&perSM, k_mega, 256, SMEM_MEGA);
        if (perSM < 1) perSM = 1;
        if (perSM > 2) perSM = 2;
        grid_mega = prop.multiProcessorCount * perSM;
    }

    k_init<<<256, 256>>>(Wa_b, b_hh0, b_hh1, b_ih0, b_ih1);
    k_cvtw<<<1024, 256>>>(Wa_w, W_hh0, W_hh1, W_ih0, W_ih1);
    k_uk<<<dim3(16, 128), 256>>>(enc, Ua_w, Ua_b);
    k_mega<<<grid_mega, 256, SMEM_MEGA>>>(enc, tgt, emb, Wa_b, Va_w, Va_b,
                                          b_ih0, b_hh0, b_ih1, b_hh1, fc_w, att);
    k_fc<<<dim3(NROW / 128, VOCAB / 128), 256, SMEM_FC>>>(fc_b, out);
    k_logsoftmax<<<NROW, 256>>>(out);
}

// round 15
// speedup vs baseline: 1.0576x; 1.0576x over previous
#include <cuda_runtime.h>
#include <cuda_bf16.h>
#include <math.h>

typedef unsigned int uint;
typedef __nv_bfloat16 bf16;

#define VOCAB 32000
#define HDIM  1024
#define EHDIM 1024
#define NB    32
#define LSEQ  128
#define XDIM  2048
#define G3H   3072
#define NROW  (NB*LSEQ)
#define NBH   (NB*HDIM)
#define NBG   (NB*G3H)

#define AROW  136
#define CHA   (32*AROW)
#define CHW   (64*AROW)
#define MSTAGE_B ((CHA+CHW)*2)     // 26112 bytes per stage
#define NSTG  3
#define MBAR_OFF  (NSTG*MSTAGE_B)
#define SMEM_MEGA (NSTG*MSTAGE_B + 64)

#define FROW  72
#define FSTAGE_B (256*144)
#define SMEM_FC  (2*FSTAGE_B + 16)
#define FBAR_OFF (2*FSTAGE_B)

#define UBUF 3456

// ---------------- scratch ----------------
__device__ __align__(256) float g_Uk[NB*LSEQ*HDIM];
__device__ __align__(256) float g_h0f[NBH];
__device__ __align__(256) float g_h1f[NBH];
__device__ __align__(256) bf16  g_qb[16*CHA];
__device__ __align__(256) bf16  g_h0b[8*CHA];
__device__ __align__(256) bf16  g_xb[16*CHA];
__device__ __align__(256) float g_Wq[NBH];
__device__ __align__(256) float g_scores[NB*LSEQ];
__device__ __align__(256) float g_gh0[NBG];
__device__ __align__(256) float g_gh1[NBG];
__device__ __align__(256) float g_gi0[NBG];
__device__ __align__(256) float g_gi1[NBG];
__device__ __align__(256) bf16  g_wWa[16*16*CHW];
__device__ __align__(256) bf16  g_wHh0[48*8*CHW];
__device__ __align__(256) bf16  g_wHh1[48*8*CHW];
__device__ __align__(256) bf16  g_wIh0[48*16*CHW];
__device__ __align__(256) bf16  g_wIh1[48*8*CHW];
__device__ __align__(256) bf16  g_fcwt[(size_t)16*VOCAB*FROW];
__device__ __align__(256) bf16  g_A2t[(size_t)16*NROW*FROW];
__device__ unsigned g_bar;
__device__ unsigned g_gen;

// ---------------- helpers ----------------
__device__ __forceinline__ float tanha(float x) {
    float r; asm("tanh.approx.f32 %0,%1;" : "=f"(r) : "f"(x)); return r;
}
__device__ __forceinline__ float sigp(float x) { return 1.f / (1.f + __expf(-x)); }
__device__ __forceinline__ float wsum(float v) {
#pragma unroll
    for (int o = 16; o > 0; o >>= 1) v += __shfl_xor_sync(0xffffffffu, v, o);
    return v;
}
__device__ __forceinline__ float wmaxr(float v) {
#pragma unroll
    for (int o = 16; o > 0; o >>= 1) v = fmaxf(v, __shfl_xor_sync(0xffffffffu, v, o));
    return v;
}

__device__ __forceinline__ void mbar_init(uint a, uint cnt) {
    asm volatile("mbarrier.init.shared::cta.b64 [%0], %1;" :: "r"(a), "r"(cnt));
}
__device__ __forceinline__ void mbar_expect(uint a, uint tx) {
    asm volatile("mbarrier.arrive.expect_tx.shared::cta.b64 _, [%0], %1;"
                 :: "r"(a), "r"(tx) : "memory");
}
__device__ __forceinline__ void bulk_g2s(uint dst, const void* src, uint bytes, uint mbar) {
    asm volatile("cp.async.bulk.shared::cta.global.mbarrier::complete_tx::bytes "
                 "[%0], [%1], %2, [%3];"
                 :: "r"(dst), "l"(src), "r"(bytes), "r"(mbar) : "memory");
}
__device__ __forceinline__ void mbar_wait(uint a, uint par) {
    asm volatile("{\n\t.reg .pred P;\nWAITL_%=:\n\t"
                 "mbarrier.try_wait.parity.shared::cta.b64 P, [%0], %1, 0x989680;\n\t"
                 "@P bra DONEL_%=;\n\tbra WAITL_%=;\nDONEL_%=:\n\t}"
                 :: "r"(a), "r"(par) : "memory");
}
__device__ __forceinline__ void fence_proxy() {
    asm volatile("fence.proxy.async.shared::cta;" ::: "memory");
}
__device__ __forceinline__ void cpa16(uint dst, const void* src) {
    asm volatile("cp.async.cg.shared.global [%0], [%1], 16;\n" :: "r"(dst), "l"(src));
}
#define CP_COMMIT asm volatile("cp.async.commit_group;\n")
#define CP_WAIT1  asm volatile("cp.async.wait_group 1;\n" ::: "memory")
#define CP_WAIT0  asm volatile("cp.async.wait_group 0;\n" ::: "memory")

__device__ __forceinline__ void mma_bf16(float* c, uint a0, uint a1, uint a2, uint a3,
                                         uint b0, uint b1) {
    asm volatile(
        "mma.sync.aligned.m16n8k16.row.col.f32.bf16.bf16.f32 "
        "{%0,%1,%2,%3}, {%4,%5,%6,%7}, {%8,%9}, {%0,%1,%2,%3};\n"
        : "+f"(c[0]), "+f"(c[1]), "+f"(c[2]), "+f"(c[3])
        : "r"(a0), "r"(a1), "r"(a2), "r"(a3), "r"(b0), "r"(b1));
}
__device__ __forceinline__ void mma_tf32(float* c, float a0, float a1, float a2, float a3,
                                         float b0, float b1) {
    asm volatile(
        "mma.sync.aligned.m16n8k8.row.col.f32.tf32.tf32.f32 "
        "{%0,%1,%2,%3},{%4,%5,%6,%7},{%8,%9},{%0,%1,%2,%3};\n"
        : "+f"(c[0]), "+f"(c[1]), "+f"(c[2]), "+f"(c[3])
        : "r"(__float_as_uint(a0)), "r"(__float_as_uint(a1)),
          "r"(__float_as_uint(a2)), "r"(__float_as_uint(a3)),
          "r"(__float_as_uint(b0)), "r"(__float_as_uint(b1)));
}

// ---------------- grid barrier ----------------
__device__ __forceinline__ void gsync(int nb) {
    __syncthreads();
    if (threadIdx.x == 0) {
        volatile unsigned* vg = &g_gen;
        unsigned gen = *vg;
        __threadfence();
        unsigned old = atomicInc(&g_bar, (unsigned)(nb - 1));
        if (old == (unsigned)(nb - 1)) {
            __threadfence();
            *vg = gen + 1;
        } else {
            while (*vg == gen) { }
            __threadfence();
        }
    }
    __syncthreads();
}

// ---------------- bf16 mma task: C[32][64@jbase] += A(4 chunks) @ W^T (atomicAdd) ------
// 3-stage pipeline, issue-ahead 2; stage parity persists across calls via par[].
__device__ void gemm_bf(const bf16* __restrict__ A, const bf16* __restrict__ W,
                        float* __restrict__ C, int ldc, int jbase,
                        char* sm, int* par) {
    const int tid = threadIdx.x;
    const int lane = tid & 31, wid = tid >> 5;
    const int warpM = wid & 1, warpN = wid >> 1;
    const int g = lane >> 2, tg = lane & 3;
    const int m0 = warpM * 16, n0 = warpN * 16;
    uint sb = (uint)__cvta_generic_to_shared(sm);
    uint mb = sb + MBAR_OFF;

    float acc[2][4];
#pragma unroll
    for (int h = 0; h < 2; h++)
#pragma unroll
        for (int u = 0; u < 4; u++) acc[h][u] = 0.f;

#define MISSUE(c) do { \
    int _s = (c) % NSTG; uint _mbar = mb + _s * 8; \
    if (tid == 0) { \
        mbar_expect(_mbar, MSTAGE_B); \
        uint _dst = sb + _s * MSTAGE_B; \
        bulk_g2s(_dst, A + (c) * CHA, CHA * 2, _mbar); \
        bulk_g2s(_dst + CHA * 2, W + (size_t)(c) * CHW, CHW * 2, _mbar); \
    } } while (0)

    MISSUE(0);
    MISSUE(1);
    for (int c = 0; c < 4; ++c) {
        if (c + 2 < 4) MISSUE(c + 2);
        int s = c % NSTG;
        mbar_wait(mb + s * 8, (uint)par[s]);
        par[s] ^= 1;
        const bf16* bA = (const bf16*)(sm + s * MSTAGE_B);
        const bf16* bW = bA + CHA;
#pragma unroll
        for (int ks = 0; ks < 8; ks++) {
            int k0 = ks * 16 + tg * 2;
            uint a0 = *(const uint*)&bA[(m0 + g) * AROW + k0];
            uint a1 = *(const uint*)&bA[(m0 + 8 + g) * AROW + k0];
            uint a2 = *(const uint*)&bA[(m0 + g) * AROW + k0 + 8];
            uint a3 = *(const uint*)&bA[(m0 + 8 + g) * AROW + k0 + 8];
            uint b0 = *(const uint*)&bW[(n0 + g) * AROW + k0];
            uint b1 = *(const uint*)&bW[(n0 + g) * AROW + k0 + 8];
            uint b2 = *(const uint*)&bW[(n0 + 8 + g) * AROW + k0];
            uint b3 = *(const uint*)&bW[(n0 + 8 + g) * AROW + k0 + 8];
            mma_bf16(acc[0], a0, a1, a2, a3, b0, b1);
            mma_bf16(acc[1], a0, a1, a2, a3, b2, b3);
        }
        __syncthreads();
    }
#undef MISSUE

#pragma unroll
    for (int h = 0; h < 2; h++) {
        int j = jbase + n0 + h * 8 + tg * 2;
        atomicAdd(&C[(size_t)(m0 + g) * ldc + j],         acc[h][0]);
        atomicAdd(&C[(size_t)(m0 + g) * ldc + j + 1],     acc[h][1]);
        atomicAdd(&C[(size_t)(m0 + 8 + g) * ldc + j],     acc[h][2]);
        atomicAdd(&C[(size_t)(m0 + 8 + g) * ldc + j + 1], acc[h][3]);
    }
}

__device__ __forceinline__ void preset3h(float* dst, const float* bias, int n) {
    float* p = dst + (size_t)n * G3H;
    for (int j = threadIdx.x; j < G3H; j += 256) p[j] = bias[j];
}
__device__ __forceinline__ void preset1h(float* dst, const float* bias, int n) {
    float* p = dst + (size_t)n * HDIM;
    for (int j = threadIdx.x; j < HDIM; j += 256) p[j] = bias[j];
}

// ---------------- persistent megakernel (2 blocks/SM) ----------------
__global__ void __launch_bounds__(256, 2) k_mega(
    const float* __restrict__ enc, const int* __restrict__ tgt,
    const float* __restrict__ emb,
    const float* __restrict__ Wa_b,
    const float* __restrict__ Va_w, const float* __restrict__ Va_b,
    const float* __restrict__ bih0, const float* __restrict__ bhh0,
    const float* __restrict__ bih1, const float* __restrict__ bhh1,
    float* __restrict__ att) {
    extern __shared__ char dynsm[];
    const int nbk = gridDim.x;
    const int tid = threadIdx.x;
    const int wid = tid >> 5, lane = tid & 31;
    const int gw = blockIdx.x * 8 + wid;
    const int NW = nbk * 8;
    const int gt = blockIdx.x * 256 + tid;
    const int NT = nbk * 256;
    const float Vab = Va_b[0];
    int par[NSTG];
#pragma unroll
    for (int s = 0; s < NSTG; s++) par[s] = 0;

    {
        uint mb = (uint)__cvta_generic_to_shared(dynsm) + MBAR_OFF;
        if (tid == 0)
            for (int s = 0; s < NSTG; s++) mbar_init(mb + s * 8, 1);
        fence_proxy();
    }
    __syncthreads();

    for (int step = 0; step < LSEQ; step++) {
        // ---- P1: Wq x4 (64) + gh0 x2 (96) + gh1 x2 (96) + preset gi1 (32)
        for (int t = blockIdx.x; t < 288; t += nbk) {
            if (t < 64) {
                int p = t >> 4, jt = t & 15;
                gemm_bf(g_qb + p * 4 * CHA, g_wWa + (size_t)(jt * 16 + p * 4) * CHW,
                        g_Wq, HDIM, jt * 64, dynsm, par);
            } else if (t < 160) {
                int u = t - 64, p = u / 48, jt = u % 48;
                gemm_bf(g_qb + p * 4 * CHA, g_wHh0 + (size_t)(jt * 8 + p * 4) * CHW,
                        g_gh0, G3H, jt * 64, dynsm, par);
            } else if (t < 256) {
                int u = t - 160, p = u / 48, jt = u % 48;
                gemm_bf(g_qb + (8 + p * 4) * CHA, g_wHh1 + (size_t)(jt * 8 + p * 4) * CHW,
                        g_gh1, G3H, jt * 64, dynsm, par);
            } else {
                preset3h(g_gi1, bih1, t - 256);
            }
        }
        gsync(nbk);

        // ---- P2a: scores (MUFU tanh.approx)
        for (int t = gw; t < NB * LSEQ; t += NW) {
            int n = t >> 7;
            const float4* uk = (const float4*)(g_Uk + (size_t)t * HDIM);
            const float4* wq = (const float4*)(g_Wq + n * HDIM);
            const float4* va = (const float4*)Va_w;
            float s = 0.f;
#pragma unroll 2
            for (int i = lane; i < 256; i += 32) {
                float4 u = uk[i], q = wq[i], v = va[i];
                s += v.x * tanha(u.x + q.x);
                s += v.y * tanha(u.y + q.y);
                s += v.z * tanha(u.z + q.z);
                s += v.w * tanha(u.w + q.w);
            }
            s = wsum(s);
            if (lane == 0) g_scores[t] = s + Vab;
        }
        gsync(nbk);

        // ---- P2c: softmax + context + embedding -> g_xb (chunk-major), att out
        for (int t = gw; t < 2048; t += NW) {
            if (t < 1024) {
                int n = t >> 5, c = t & 31, d = c * 32 + lane;
                const float* sc = g_scores + n * LSEQ;
                float e[4];
                float m0 = fmaxf(fmaxf(sc[lane * 4 + 0], sc[lane * 4 + 1]),
                                 fmaxf(sc[lane * 4 + 2], sc[lane * 4 + 3]));
                float mx = wmaxr(m0);
                float lsum = 0.f;
#pragma unroll
                for (int i = 0; i < 4; i++) { e[i] = __expf(sc[lane * 4 + i] - mx); lsum += e[i]; }
                float inv = __fdividef(1.f, wsum(lsum));
                if (c == 0) {
                    float* ap = att + ((size_t)n * LSEQ + step) * LSEQ + lane * 4;
#pragma unroll
                    for (int i = 0; i < 4; i++) ap[i] = e[i] * inv;
                }
                float ctx0 = 0.f, ctx1 = 0.f;
                const float* ep = enc + (size_t)n * EHDIM + d;
#pragma unroll 4
                for (int l = 0; l < LSEQ; l += 2) {
                    float w0 = __shfl_sync(0xffffffffu, e[l & 3], l >> 2);
                    float w1 = __shfl_sync(0xffffffffu, e[(l + 1) & 3], (l + 1) >> 2);
                    ctx0 += w0 * ep[(size_t)l * (NB * EHDIM)];
                    ctx1 += w1 * ep[(size_t)(l + 1) * (NB * EHDIM)];
                }
                g_xb[(d >> 7) * CHA + n * AROW + (d & 127)] =
                    __float2bfloat16((ctx0 + ctx1) * inv);
            } else {
                int u = t - 1024;
                int n = u >> 5, c = u & 31, j = c * 32 + lane;
                int tok = tgt[n * LSEQ + step];
                g_xb[(8 + (j >> 7)) * CHA + n * AROW + (j & 127)] =
                    __float2bfloat16(emb[(size_t)tok * HDIM + j]);
            }
        }
        gsync(nbk);

        // ---- P3: gi0 x4 (192) + preset Wq (32)
        for (int t = blockIdx.x; t < 224; t += nbk) {
            if (t < 192) {
                int p = t / 48, jt = t % 48;
                gemm_bf(g_xb + p * 4 * CHA, g_wIh0 + (size_t)(jt * 16 + p * 4) * CHW,
                        g_gi0, G3H, jt * 64, dynsm, par);
            } else {
                preset1h(g_Wq, Wa_b, t - 192);
            }
        }
        gsync(nbk);

        // ---- comb0 -> h0; preset gh0 in place
        for (int i = gt; i < NBH; i += NT) {
            int n = i >> 10, j = i & 1023;
            int b = n * G3H + j;
            float r = sigp(g_gi0[b] + g_gh0[b]);
            float z = sigp(g_gi0[b + HDIM] + g_gh0[b + HDIM]);
            float nn = tanhf(g_gi0[b + 2 * HDIM] + r * g_gh0[b + 2 * HDIM]);
            float h = (1.f - z) * nn + z * g_h0f[i];
            g_h0f[i] = h;
            bf16 hb = __float2bfloat16(h);
            int ca = (j >> 7) * CHA + n * AROW + (j & 127);
            g_h0b[ca] = hb;
            g_qb[ca] = hb;
            g_gh0[b] = bhh0[j];
            g_gh0[b + HDIM] = bhh0[j + HDIM];
            g_gh0[b + 2 * HDIM] = bhh0[j + 2 * HDIM];
        }
        gsync(nbk);

        // ---- P4: gi1 x2 (96) + preset gi0 (32)
        for (int t = blockIdx.x; t < 128; t += nbk) {
            if (t < 96) {
                int p = t / 48, jt = t % 48;
                gemm_bf(g_h0b + p * 4 * CHA, g_wIh1 + (size_t)(jt * 8 + p * 4) * CHW,
                        g_gi1, G3H, jt * 64, dynsm, par);
            } else {
                preset3h(g_gi0, bih0, t - 96);
            }
        }
        gsync(nbk);

        // ---- comb1 -> h1, A2t; preset gh1 in place
        for (int i = gt; i < NBH; i += NT) {
            int n = i >> 10, j = i & 1023;
            int b = n * G3H + j;
            float r = sigp(g_gi1[b] + g_gh1[b]);
            float z = sigp(g_gi1[b + HDIM] + g_gh1[b + HDIM]);
            float nn = tanhf(g_gi1[b + 2 * HDIM] + r * g_gh1[b + 2 * HDIM]);
            float h = (1.f - z) * nn + z * g_h1f[i];
            g_h1f[i] = h;
            bf16 hb = __float2bfloat16(h);
            g_qb[(8 + (j >> 7)) * CHA + n * AROW + (j & 127)] = hb;
            g_A2t[((size_t)(j >> 6) * NROW + step * NB + n) * FROW + (j & 63)] = hb;
            g_gh1[b] = bhh1[j];
            g_gh1[b + HDIM] = bhh1[j + HDIM];
            g_gh1[b + 2 * HDIM] = bhh1[j + 2 * HDIM];
        }
        gsync(nbk);
    }
}

// ---------------- init ----------------
__global__ void k_init(const float* __restrict__ Wa_b,
                       const float* __restrict__ bhh0, const float* __restrict__ bhh1,
                       const float* __restrict__ bih0, const float* __restrict__ bih1) {
    int i0 = blockIdx.x * 256 + threadIdx.x;
    int st = gridDim.x * 256;
    if (i0 == 0) { g_bar = 0; g_gen = 0; }
    bf16 z = __float2bfloat16(0.f);
    for (int i = i0; i < NBH; i += st) {
        g_h0f[i] = 0.f; g_h1f[i] = 0.f;
        g_Wq[i] = Wa_b[i & 1023];
    }
    for (int i = i0; i < 16 * CHA; i += st) g_qb[i] = z;
    for (int i = i0; i < 8 * CHA; i += st) g_h0b[i] = z;
    for (int i = i0; i < NBG; i += st) {
        int j = i % G3H;
        g_gh0[i] = bhh0[j]; g_gh1[i] = bhh1[j];
        g_gi0[i] = bih0[j]; g_gi1[i] = bih1[j];
    }
}

// ---------------- weight conversion ----------------
__global__ void k_cvtw(const float* __restrict__ wa, const float* __restrict__ hh0,
                       const float* __restrict__ hh1, const float* __restrict__ ih0,
                       const float* __restrict__ ih1, const float* __restrict__ fcw) {
    long st = (long)gridDim.x * blockDim.x;
    long i0 = (long)blockIdx.x * blockDim.x + threadIdx.x;
    for (long i = i0; i < (long)HDIM * XDIM; i += st) {
        int j = (int)(i >> 11), k = (int)(i & 2047);
        g_wWa[(size_t)((j >> 6) * 16 + (k >> 7)) * CHW + (j & 63) * AROW + (k & 127)] =
            __float2bfloat16(wa[i]);
    }
    for (long i = i0; i < (long)G3H * HDIM; i += st) {
        int j = (int)(i >> 10), k = (int)(i & 1023);
        size_t o = (size_t)((j >> 6) * 8 + (k >> 7)) * CHW + (j & 63) * AROW + (k & 127);
        g_wHh0[o] = __float2bfloat16(hh0[i]);
        g_wHh1[o] = __float2bfloat16(hh1[i]);
        g_wIh1[o] = __float2bfloat16(ih1[i]);
    }
    for (long i = i0; i < (long)G3H * XDIM; i += st) {
        int j = (int)(i >> 11), k = (int)(i & 2047);
        g_wIh0[(size_t)((j >> 6) * 16 + (k >> 7)) * CHW + (j & 63) * AROW + (k & 127)] =
            __float2bfloat16(ih0[i]);
    }
    for (long i = i0; i < (long)VOCAB * HDIM; i += st) {
        int v = (int)(i >> 10), k = (int)(i & 1023);
        g_fcwt[((size_t)(k >> 6) * VOCAB + v) * FROW + (k & 63)] = __float2bfloat16(fcw[i]);
    }
}

// ---------------- Uk = keys @ Ua_w^T + Ua_b (tf32 mma, once) ----------------
__global__ void __launch_bounds__(256) k_uk(const float* __restrict__ enc,
                                            const float* __restrict__ Uw,
                                            const float* __restrict__ Ub) {
    __shared__ float sm[2 * UBUF];
    const int bm = blockIdx.y, bn = blockIdx.x;
    const int tid = threadIdx.x;
    const int lane = tid & 31, wid = tid >> 5;
    const int warpM = wid & 1, warpN = wid >> 1;
    const int g = lane >> 2, tg = lane & 3;
    const int am = tid >> 3, ak = (tid & 7) << 2;

    int r = bm * 32 + am;
    const float* Arow = enc + ((size_t)(r & 127) * NB + (r >> 7)) * EHDIM;

    float acc[2][4];
#pragma unroll
    for (int h = 0; h < 2; h++)
#pragma unroll
        for (int u = 0; u < 4; u++) acc[h][u] = 0.f;

    uint sb = (uint)__cvta_generic_to_shared(sm);

#define UISSUE(c) do { \
    uint _b = sb + (uint)(((c) & 1) * UBUF) * 4; \
    int _ko = (c) * 32; \
    cpa16(_b + (uint)(am * 36 + ak) * 4, Arow + _ko + ak); \
    _Pragma("unroll") \
    for (int _i = 0; _i < 2; _i++) { \
        int _idx = tid + _i * 256; \
        int _wn = _idx >> 3, _wk = (_idx & 7) << 2; \
        cpa16(_b + (uint)(32 * 36 + _wn * 36 + _wk) * 4, \
              Uw + (size_t)(bn * 64 + _wn) * EHDIM + _ko + _wk); \
    } } while (0)

    UISSUE(0); CP_COMMIT;
    for (int c = 0; c < 32; ++c) {
        if (c + 1 < 32) { UISSUE(c + 1); CP_COMMIT; CP_WAIT1; }
        else { CP_WAIT0; }
        __syncthreads();
        const float* bA = sm + (c & 1) * UBUF;
        const float* bW = bA + 32 * 36;
        int ar = (warpM * 16 + g) * 36;
        int br = (warpN * 16 + g) * 36;
#pragma unroll
        for (int kk = 0; kk < 4; kk++) {
            int ko = kk * 8 + tg;
            float a0 = bA[ar + ko],       a1 = bA[ar + 288 + ko];
            float a2 = bA[ar + ko + 4],   a3 = bA[ar + 288 + ko + 4];
            float b0 = bW[br + ko],       b1 = bW[br + ko + 4];
            float b2 = bW[br + 288 + ko], b3 = bW[br + 288 + ko + 4];
            mma_tf32(acc[0], a0, a1, a2, a3, b0, b1);
            mma_tf32(acc[1], a0, a1, a2, a3, b2, b3);
        }
        __syncthreads();
    }
#undef UISSUE

    int m = bm * 32 + warpM * 16 + g;
#pragma unroll
    for (int h = 0; h < 2; h++) {
        int j = bn * 64 + warpN * 16 + h * 8 + tg * 2;
        float bb0 = Ub[j], bb1 = Ub[j + 1];
        g_Uk[(size_t)m * HDIM + j]           = acc[h][0] + bb0;
        g_Uk[(size_t)m * HDIM + j + 1]       = acc[h][1] + bb1;
        g_Uk[(size_t)(m + 8) * HDIM + j]     = acc[h][2] + bb0;
        g_Uk[(size_t)(m + 8) * HDIM + j + 1] = acc[h][3] + bb1;
    }
}

// ---------------- FC: 128x128 bf16 tiles; bm fast-varying for fcw reuse ----------------
__global__ void __launch_bounds__(256, 2) k_fc(const float* __restrict__ fcb,
                                               float* __restrict__ out) {
    extern __shared__ char dynsm[];
    int bm = blockIdx.x, bn = blockIdx.y;
    int tid = threadIdx.x, wid = tid >> 5, lane = tid & 31;
    int g = lane >> 2, tg = lane & 3;
    int warpM = wid >> 2, warpN = wid & 3;
    uint sb = (uint)__cvta_generic_to_shared(dynsm);
    uint mb = sb + FBAR_OFF;
    int ph[2] = {0, 0};

    if (tid == 0) { mbar_init(mb, 1); mbar_init(mb + 8, 1); }
    fence_proxy();
    __syncthreads();

    float acc[4][4][4];
#pragma unroll
    for (int a = 0; a < 4; a++)
#pragma unroll
        for (int b = 0; b < 4; b++)
#pragma unroll
            for (int c = 0; c < 4; c++) acc[a][b][c] = 0.f;

    const bf16* Ag = g_A2t + (size_t)bm * 128 * FROW;
    const bf16* Bg = g_fcwt + (size_t)bn * 128 * FROW;

#define FISSUE(kt) do { \
    int _s = (kt) & 1; uint _mbar = mb + _s * 8; \
    if (tid == 0) { \
        mbar_expect(_mbar, FSTAGE_B); \
        uint _dst = sb + _s * FSTAGE_B; \
        bulk_g2s(_dst, Ag + (size_t)(kt) * (NROW * FROW), 128 * 144, _mbar); \
        bulk_g2s(_dst + 128 * 144, Bg + (size_t)(kt) * ((size_t)VOCAB * FROW), 128 * 144, _mbar); \
    } } while (0)

    FISSUE(0);
    for (int kt = 0; kt < 16; kt++) {
        if (kt + 1 < 16) FISSUE(kt + 1);
        int s = kt & 1;
        mbar_wait(mb + s * 8, (uint)ph[s]);
        ph[s] ^= 1;
        const bf16* As = (const bf16*)(dynsm + s * FSTAGE_B);
        const bf16* Bs = As + 128 * FROW;
#pragma unroll
        for (int ks = 0; ks < 4; ks++) {
            int k0 = ks * 16 + tg * 2;
            uint af[4][4], bf[4][2];
#pragma unroll
            for (int mt = 0; mt < 4; mt++) {
                int mrow = warpM * 64 + mt * 16 + g;
                af[mt][0] = *(const uint*)&As[mrow * FROW + k0];
                af[mt][1] = *(const uint*)&As[(mrow + 8) * FROW + k0];
                af[mt][2] = *(const uint*)&As[mrow * FROW + k0 + 8];
                af[mt][3] = *(const uint*)&As[(mrow + 8) * FROW + k0 + 8];
            }
#pragma unroll
            for (int nt = 0; nt < 4; nt++) {
                int nrow = warpN * 32 + nt * 8 + g;
                bf[nt][0] = *(const uint*)&Bs[nrow * FROW + k0];
                bf[nt][1] = *(const uint*)&Bs[nrow * FROW + k0 + 8];
            }
#pragma unroll
            for (int mt = 0; mt < 4; mt++)
#pragma unroll
                for (int nt = 0; nt < 4; nt++)
                    mma_bf16(acc[mt][nt], af[mt][0], af[mt][1], af[mt][2], af[mt][3],
                             bf[nt][0], bf[nt][1]);
        }
        __syncthreads();
    }
#undef FISSUE

#pragma unroll
    for (int mt = 0; mt < 4; mt++) {
#pragma unroll
        for (int nt = 0; nt < 4; nt++) {
            int r0 = bm * 128 + warpM * 64 + mt * 16 + g;
            int c = bn * 128 + warpN * 32 + nt * 8 + tg * 2;
            float bv0 = fcb[c], bv1 = fcb[c + 1];
            {
                int l = r0 >> 5, n = r0 & 31;
                float* p = out + ((size_t)(n * LSEQ + l)) * VOCAB + c;
                p[0] = acc[mt][nt][0] + bv0;
                p[1] = acc[mt][nt][1] + bv1;
            }
            {
                int r1 = r0 + 8;
                int l = r1 >> 5, n = r1 & 31;
                float* p = out + ((size_t)(n * LSEQ + l)) * VOCAB + c;
                p[0] = acc[mt][nt][2] + bv0;
                p[1] = acc[mt][nt][3] + bv1;
            }
        }
    }
}

// ---------------- log_softmax ----------------
__global__ void k_logsoftmax(float* __restrict__ out) {
    __shared__ float rm[256], rs[256];
    int row = blockIdx.x;
    float* p = out + (size_t)row * VOCAB;
    int t = threadIdx.x;
    float m = -1e30f, s = 0.f;
    for (int i = t; i < VOCAB; i += 256) {
        float v = p[i];
        if (v > m) { s = s * __expf(m - v) + 1.f; m = v; }
        else s += __expf(v - m);
    }
    rm[t] = m; rs[t] = s; __syncthreads();
    for (int o = 128; o > 0; o >>= 1) {
        if (t < o) {
            float m2 = rm[t + o], s2 = rs[t + o];
            float M = fmaxf(rm[t], m2);
            rs[t] = rs[t] * __expf(rm[t] - M) + s2 * __expf(m2 - M);
            rm[t] = M;
        }
        __syncthreads();
    }
    float lse = rm[0] + logf(rs[0]);
    for (int i = t; i < VOCAB; i += 256) p[i] -= lse;
}

// ---------------- launch ----------------
extern "C" void kernel_launch(void* const* d_in, const int* in_sizes, int n_in,
                              void* d_out, int out_size) {
    (void)in_sizes; (void)n_in; (void)out_size;
    const float* enc   = (const float*)d_in[0];
    const int*   tgt   = (const int*)  d_in[1];
    const float* emb   = (const float*)d_in[2];
    const float* Wa_w  = (const float*)d_in[3];
    const float* Wa_b  = (const float*)d_in[4];
    const float* Ua_w  = (const float*)d_in[5];
    const float* Ua_b  = (const float*)d_in[6];
    const float* Va_w  = (const float*)d_in[7];
    const float* Va_b  = (const float*)d_in[8];
    const float* W_ih0 = (const float*)d_in[9];
    const float* W_hh0 = (const float*)d_in[10];
    const float* b_ih0 = (const float*)d_in[11];
    const float* b_hh0 = (const float*)d_in[12];
    const float* W_ih1 = (const float*)d_in[13];
    const float* W_hh1 = (const float*)d_in[14];
    const float* b_ih1 = (const float*)d_in[15];
    const float* b_hh1 = (const float*)d_in[16];
    const float* fc_w  = (const float*)d_in[17];
    const float* fc_b  = (const float*)d_in[18];

    float* out = (float*)d_out;
    float* att = out + (size_t)NB * LSEQ * VOCAB;

    static int grid_mega = 0;
    if (grid_mega == 0) {
        cudaFuncSetAttribute(k_mega, cudaFuncAttributeMaxDynamicSharedMemorySize, SMEM_MEGA);
        cudaFuncSetAttribute(k_fc,   cudaFuncAttributeMaxDynamicSharedMemorySize, SMEM_FC);
        int dev = 0;
        cudaGetDevice(&dev);
        cudaDeviceProp prop;
        cudaGetDeviceProperties(&prop, dev);
        int perSM = 1;
        cudaOccupancyMaxActiveBlocksPerMultiprocessor(&perSM, k_mega, 256, SMEM_MEGA);
        if (perSM < 1) perSM = 1;
        if (perSM > 2) perSM = 2;
        grid_mega = prop.multiProcessorCount * perSM;
    }

    k_init<<<256, 256>>>(Wa_b, b_hh0, b_hh1, b_ih0, b_ih1);
    k_cvtw<<<2048, 256>>>(Wa_w, W_hh0, W_hh1, W_ih0, W_ih1, fc_w);
    k_uk<<<dim3(16, 128), 256>>>(enc, Ua_w, Ua_b);
    k_mega<<<grid_mega, 256, SMEM_MEGA>>>(enc, tgt, emb, Wa_b, Va_w, Va_b,
                                          b_ih0, b_hh0, b_ih1, b_hh1, att);
    k_fc<<<dim3(NROW / 128, VOCAB / 128), 256, SMEM_FC>>>(fc_b, out);
    k_logsoftmax<<<NROW, 256>>>(out);
}

// round 17
// speedup vs baseline: 1.0624x; 1.0046x over previous
#include <cuda_runtime.h>
#include <cuda_bf16.h>
#include <math.h>

typedef unsigned int uint;
typedef __nv_bfloat16 bf16;

#define VOCAB 32000
#define HDIM  1024
#define EHDIM 1024
#define NB    32
#define LSEQ  128
#define XDIM  2048
#define G3H   3072
#define NROW  (NB*LSEQ)
#define NBH   (NB*HDIM)
#define NBG   (NB*G3H)

#define AROW  136
#define CHA   (32*AROW)
#define CHW   (64*AROW)
#define MSTAGE_B ((CHA+CHW)*2)     // 26112 bytes per stage
#define NSTG  3
#define MBAR_OFF  (NSTG*MSTAGE_B)
#define SMEM_MEGA (NSTG*MSTAGE_B + 64)

#define FROW  72
#define FSTAGE_B (256*144)
#define SMEM_FC  (2*FSTAGE_B + 16)
#define FBAR_OFF (2*FSTAGE_B)

#define UBUF 3456

// ---------------- scratch ----------------
__device__ __align__(256) float g_Uk[NB*LSEQ*HDIM];
__device__ __align__(256) float g_h0f[NBH];
__device__ __align__(256) float g_h1f[NBH];
__device__ __align__(256) bf16  g_qb[16*CHA];
__device__ __align__(256) bf16  g_h0b[8*CHA];
__device__ __align__(256) bf16  g_xb[16*CHA];
__device__ __align__(256) float g_Wq[NBH];
__device__ __align__(256) float g_scores[NB*LSEQ];
__device__ __align__(256) float g_gh0[NBG];
__device__ __align__(256) float g_gh1[NBG];
__device__ __align__(256) float g_gi0[NBG];
__device__ __align__(256) float g_gi1[NBG];
__device__ __align__(256) bf16  g_wWa[16*16*CHW];
__device__ __align__(256) bf16  g_wHh0[48*8*CHW];
__device__ __align__(256) bf16  g_wHh1[48*8*CHW];
__device__ __align__(256) bf16  g_wIh0[48*16*CHW];
__device__ __align__(256) bf16  g_wIh1[48*8*CHW];
__device__ __align__(256) bf16  g_fcwt[(size_t)16*VOCAB*FROW];
__device__ __align__(256) bf16  g_A2t[(size_t)16*NROW*FROW];
__device__ unsigned g_bar;
__device__ unsigned g_gen;

// ---------------- helpers ----------------
__device__ __forceinline__ float tanha(float x) {
    float r; asm("tanh.approx.f32 %0,%1;" : "=f"(r) : "f"(x)); return r;
}
__device__ __forceinline__ float sigp(float x) { return 1.f / (1.f + __expf(-x)); }
__device__ __forceinline__ float wsum(float v) {
#pragma unroll
    for (int o = 16; o > 0; o >>= 1) v += __shfl_xor_sync(0xffffffffu, v, o);
    return v;
}
__device__ __forceinline__ float wmaxr(float v) {
#pragma unroll
    for (int o = 16; o > 0; o >>= 1) v = fmaxf(v, __shfl_xor_sync(0xffffffffu, v, o));
    return v;
}

__device__ __forceinline__ void mbar_init(uint a, uint cnt) {
    asm volatile("mbarrier.init.shared::cta.b64 [%0], %1;" :: "r"(a), "r"(cnt));
}
__device__ __forceinline__ void mbar_expect(uint a, uint tx) {
    asm volatile("mbarrier.arrive.expect_tx.shared::cta.b64 _, [%0], %1;"
                 :: "r"(a), "r"(tx) : "memory");
}
__device__ __forceinline__ void bulk_g2s(uint dst, const void* src, uint bytes, uint mbar) {
    asm volatile("cp.async.bulk.shared::cta.global.mbarrier::complete_tx::bytes "
                 "[%0], [%1], %2, [%3];"
                 :: "r"(dst), "l"(src), "r"(bytes), "r"(mbar) : "memory");
}
__device__ __forceinline__ void mbar_wait(uint a, uint par) {
    asm volatile("{\n\t.reg .pred P;\nWAITL_%=:\n\t"
                 "mbarrier.try_wait.parity.shared::cta.b64 P, [%0], %1, 0x989680;\n\t"
                 "@P bra DONEL_%=;\n\tbra WAITL_%=;\nDONEL_%=:\n\t}"
                 :: "r"(a), "r"(par) : "memory");
}
__device__ __forceinline__ void fence_proxy() {
    asm volatile("fence.proxy.async.shared::cta;" ::: "memory");
}
__device__ __forceinline__ void cpa16(uint dst, const void* src) {
    asm volatile("cp.async.cg.shared.global [%0], [%1], 16;\n" :: "r"(dst), "l"(src));
}
#define CP_COMMIT asm volatile("cp.async.commit_group;\n")
#define CP_WAIT1  asm volatile("cp.async.wait_group 1;\n" ::: "memory")
#define CP_WAIT0  asm volatile("cp.async.wait_group 0;\n" ::: "memory")

__device__ __forceinline__ void mma_bf16(float* c, uint a0, uint a1, uint a2, uint a3,
                                         uint b0, uint b1) {
    asm volatile(
        "mma.sync.aligned.m16n8k16.row.col.f32.bf16.bf16.f32 "
        "{%0,%1,%2,%3}, {%4,%5,%6,%7}, {%8,%9}, {%0,%1,%2,%3};\n"
        : "+f"(c[0]), "+f"(c[1]), "+f"(c[2]), "+f"(c[3])
        : "r"(a0), "r"(a1), "r"(a2), "r"(a3), "r"(b0), "r"(b1));
}
__device__ __forceinline__ void mma_tf32(float* c, float a0, float a1, float a2, float a3,
                                         float b0, float b1) {
    asm volatile(
        "mma.sync.aligned.m16n8k8.row.col.f32.tf32.tf32.f32 "
        "{%0,%1,%2,%3},{%4,%5,%6,%7},{%8,%9},{%0,%1,%2,%3};\n"
        : "+f"(c[0]), "+f"(c[1]), "+f"(c[2]), "+f"(c[3])
        : "r"(__float_as_uint(a0)), "r"(__float_as_uint(a1)),
          "r"(__float_as_uint(a2)), "r"(__float_as_uint(a3)),
          "r"(__float_as_uint(b0)), "r"(__float_as_uint(b1)));
}

// ---------------- grid barrier ----------------
__device__ __forceinline__ void gsync(int nb) {
    __syncthreads();
    if (threadIdx.x == 0) {
        volatile unsigned* vg = &g_gen;
        unsigned gen = *vg;
        __threadfence();
        unsigned old = atomicInc(&g_bar, (unsigned)(nb - 1));
        if (old == (unsigned)(nb - 1)) {
            __threadfence();
            *vg = gen + 1;
        } else {
            while (*vg == gen) { }
            __threadfence();
        }
    }
    __syncthreads();
}

// ---------------- bf16 mma task: C[32][64@jbase] += A(4 chunks) @ W^T (atomicAdd) ------
// 3-stage pipeline, issue-ahead 2; stage parity persists across calls via par[].
__device__ void gemm_bf(const bf16* __restrict__ A, const bf16* __restrict__ W,
                        float* __restrict__ C, int ldc, int jbase,
                        char* sm, int* par) {
    const int tid = threadIdx.x;
    const int lane = tid & 31, wid = tid >> 5;
    const int warpM = wid & 1, warpN = wid >> 1;
    const int g = lane >> 2, tg = lane & 3;
    const int m0 = warpM * 16, n0 = warpN * 16;
    uint sb = (uint)__cvta_generic_to_shared(sm);
    uint mb = sb + MBAR_OFF;

    float acc[2][4];
#pragma unroll
    for (int h = 0; h < 2; h++)
#pragma unroll
        for (int u = 0; u < 4; u++) acc[h][u] = 0.f;

#define MISSUE(c) do { \
    int _s = (c) % NSTG; uint _mbar = mb + _s * 8; \
    if (tid == 0) { \
        mbar_expect(_mbar, MSTAGE_B); \
        uint _dst = sb + _s * MSTAGE_B; \
        bulk_g2s(_dst, A + (c) * CHA, CHA * 2, _mbar); \
        bulk_g2s(_dst + CHA * 2, W + (size_t)(c) * CHW, CHW * 2, _mbar); \
    } } while (0)

    MISSUE(0);
    MISSUE(1);
    for (int c = 0; c < 4; ++c) {
        if (c + 2 < 4) MISSUE(c + 2);
        int s = c % NSTG;
        mbar_wait(mb + s * 8, (uint)par[s]);
        par[s] ^= 1;
        const bf16* bA = (const bf16*)(sm + s * MSTAGE_B);
        const bf16* bW = bA + CHA;
#pragma unroll
        for (int ks = 0; ks < 8; ks++) {
            int k0 = ks * 16 + tg * 2;
            uint a0 = *(const uint*)&bA[(m0 + g) * AROW + k0];
            uint a1 = *(const uint*)&bA[(m0 + 8 + g) * AROW + k0];
            uint a2 = *(const uint*)&bA[(m0 + g) * AROW + k0 + 8];
            uint a3 = *(const uint*)&bA[(m0 + 8 + g) * AROW + k0 + 8];
            uint b0 = *(const uint*)&bW[(n0 + g) * AROW + k0];
            uint b1 = *(const uint*)&bW[(n0 + g) * AROW + k0 + 8];
            uint b2 = *(const uint*)&bW[(n0 + 8 + g) * AROW + k0];
            uint b3 = *(const uint*)&bW[(n0 + 8 + g) * AROW + k0 + 8];
            mma_bf16(acc[0], a0, a1, a2, a3, b0, b1);
            mma_bf16(acc[1], a0, a1, a2, a3, b2, b3);
        }
        __syncthreads();
    }
#undef MISSUE

#pragma unroll
    for (int h = 0; h < 2; h++) {
        int j = jbase + n0 + h * 8 + tg * 2;
        atomicAdd(&C[(size_t)(m0 + g) * ldc + j],         acc[h][0]);
        atomicAdd(&C[(size_t)(m0 + g) * ldc + j + 1],     acc[h][1]);
        atomicAdd(&C[(size_t)(m0 + 8 + g) * ldc + j],     acc[h][2]);
        atomicAdd(&C[(size_t)(m0 + 8 + g) * ldc + j + 1], acc[h][3]);
    }
}

__device__ __forceinline__ void preset3h(float* dst, const float* bias, int n) {
    float* p = dst + (size_t)n * G3H;
    for (int j = threadIdx.x; j < G3H; j += 256) p[j] = bias[j];
}
__device__ __forceinline__ void preset1h(float* dst, const float* bias, int n) {
    float* p = dst + (size_t)n * HDIM;
    for (int j = threadIdx.x; j < HDIM; j += 256) p[j] = bias[j];
}

// ---------------- persistent megakernel (2 blocks/SM) ----------------
__global__ void __launch_bounds__(256, 2) k_mega(
    const float* __restrict__ enc, const int* __restrict__ tgt,
    const float* __restrict__ emb,
    const float* __restrict__ Wa_b,
    const float* __restrict__ Va_w, const float* __restrict__ Va_b,
    const float* __restrict__ bih0, const float* __restrict__ bhh0,
    const float* __restrict__ bih1, const float* __restrict__ bhh1,
    float* __restrict__ att) {
    extern __shared__ char dynsm[];
    const int nbk = gridDim.x;
    const int tid = threadIdx.x;
    const int wid = tid >> 5, lane = tid & 31;
    const int gw = blockIdx.x * 8 + wid;
    const int NW = nbk * 8;
    const int gt = blockIdx.x * 256 + tid;
    const int NT = nbk * 256;
    const float Vab = Va_b[0];
    int par[NSTG];
#pragma unroll
    for (int s = 0; s < NSTG; s++) par[s] = 0;

    {
        uint mb = (uint)__cvta_generic_to_shared(dynsm) + MBAR_OFF;
        if (tid == 0)
            for (int s = 0; s < NSTG; s++) mbar_init(mb + s * 8, 1);
        fence_proxy();
    }
    __syncthreads();

    for (int step = 0; step < LSEQ; step++) {
        // ---- P1: Wq x4 (64) + gh0 x2 (96) + gh1 x2 (96) + preset gi1 (32)
        for (int t = blockIdx.x; t < 288; t += nbk) {
            if (t < 64) {
                int p = t >> 4, jt = t & 15;
                gemm_bf(g_qb + p * 4 * CHA, g_wWa + (size_t)(jt * 16 + p * 4) * CHW,
                        g_Wq, HDIM, jt * 64, dynsm, par);
            } else if (t < 160) {
                int u = t - 64, p = u / 48, jt = u % 48;
                gemm_bf(g_qb + p * 4 * CHA, g_wHh0 + (size_t)(jt * 8 + p * 4) * CHW,
                        g_gh0, G3H, jt * 64, dynsm, par);
            } else if (t < 256) {
                int u = t - 160, p = u / 48, jt = u % 48;
                gemm_bf(g_qb + (8 + p * 4) * CHA, g_wHh1 + (size_t)(jt * 8 + p * 4) * CHW,
                        g_gh1, G3H, jt * 64, dynsm, par);
            } else {
                preset3h(g_gi1, bih1, t - 256);
            }
        }
        gsync(nbk);

        // ---- P2a: scores (MUFU tanh.approx)
        for (int t = gw; t < NB * LSEQ; t += NW) {
            int n = t >> 7;
            const float4* uk = (const float4*)(g_Uk + (size_t)t * HDIM);
            const float4* wq = (const float4*)(g_Wq + n * HDIM);
            const float4* va = (const float4*)Va_w;
            float s = 0.f;
#pragma unroll 2
            for (int i = lane; i < 256; i += 32) {
                float4 u = uk[i], q = wq[i], v = va[i];
                s += v.x * tanha(u.x + q.x);
                s += v.y * tanha(u.y + q.y);
                s += v.z * tanha(u.z + q.z);
                s += v.w * tanha(u.w + q.w);
            }
            s = wsum(s);
            if (lane == 0) g_scores[t] = s + Vab;
        }
        gsync(nbk);

        // ---- P2c: softmax + context + embedding -> g_xb (chunk-major), att out
        for (int t = gw; t < 2048; t += NW) {
            if (t < 1024) {
                int n = t >> 5, c = t & 31, d = c * 32 + lane;
                const float* sc = g_scores + n * LSEQ;
                float e[4];
                float m0 = fmaxf(fmaxf(sc[lane * 4 + 0], sc[lane * 4 + 1]),
                                 fmaxf(sc[lane * 4 + 2], sc[lane * 4 + 3]));
                float mx = wmaxr(m0);
                float lsum = 0.f;
#pragma unroll
                for (int i = 0; i < 4; i++) { e[i] = __expf(sc[lane * 4 + i] - mx); lsum += e[i]; }
                float inv = __fdividef(1.f, wsum(lsum));
                if (c == 0) {
                    float* ap = att + ((size_t)n * LSEQ + step) * LSEQ + lane * 4;
#pragma unroll
                    for (int i = 0; i < 4; i++) ap[i] = e[i] * inv;
                }
                float ctx0 = 0.f, ctx1 = 0.f;
                const float* ep = enc + (size_t)n * EHDIM + d;
#pragma unroll 4
                for (int l = 0; l < LSEQ; l += 2) {
                    float w0 = __shfl_sync(0xffffffffu, e[l & 3], l >> 2);
                    float w1 = __shfl_sync(0xffffffffu, e[(l + 1) & 3], (l + 1) >> 2);
                    ctx0 += w0 * ep[(size_t)l * (NB * EHDIM)];
                    ctx1 += w1 * ep[(size_t)(l + 1) * (NB * EHDIM)];
                }
                g_xb[(d >> 7) * CHA + n * AROW + (d & 127)] =
                    __float2bfloat16((ctx0 + ctx1) * inv);
            } else {
                int u = t - 1024;
                int n = u >> 5, c = u & 31, j = c * 32 + lane;
                int tok = tgt[n * LSEQ + step];
                g_xb[(8 + (j >> 7)) * CHA + n * AROW + (j & 127)] =
                    __float2bfloat16(emb[(size_t)tok * HDIM + j]);
            }
        }
        gsync(nbk);

        // ---- P3: gi0 x4 (192) + preset Wq (32)
        for (int t = blockIdx.x; t < 224; t += nbk) {
            if (t < 192) {
                int p = t / 48, jt = t % 48;
                gemm_bf(g_xb + p * 4 * CHA, g_wIh0 + (size_t)(jt * 16 + p * 4) * CHW,
                        g_gi0, G3H, jt * 64, dynsm, par);
            } else {
                preset1h(g_Wq, Wa_b, t - 192);
            }
        }
        gsync(nbk);

        // ---- comb0 -> h0; preset gh0 in place
        for (int i = gt; i < NBH; i += NT) {
            int n = i >> 10, j = i & 1023;
            int b = n * G3H + j;
            float r = sigp(g_gi0[b] + g_gh0[b]);
            float z = sigp(g_gi0[b + HDIM] + g_gh0[b + HDIM]);
            float nn = tanhf(g_gi0[b + 2 * HDIM] + r * g_gh0[b + 2 * HDIM]);
            float h = (1.f - z) * nn + z * g_h0f[i];
            g_h0f[i] = h;
            bf16 hb = __float2bfloat16(h);
            int ca = (j >> 7) * CHA + n * AROW + (j & 127);
            g_h0b[ca] = hb;
            g_qb[ca] = hb;
            g_gh0[b] = bhh0[j];
            g_gh0[b + HDIM] = bhh0[j + HDIM];
            g_gh0[b + 2 * HDIM] = bhh0[j + 2 * HDIM];
        }
        gsync(nbk);

        // ---- P4: gi1 x2 (96) + preset gi0 (32)
        for (int t = blockIdx.x; t < 128; t += nbk) {
            if (t < 96) {
                int p = t / 48, jt = t % 48;
                gemm_bf(g_h0b + p * 4 * CHA, g_wIh1 + (size_t)(jt * 8 + p * 4) * CHW,
                        g_gi1, G3H, jt * 64, dynsm, par);
            } else {
                preset3h(g_gi0, bih0, t - 96);
            }
        }
        gsync(nbk);

        // ---- comb1 -> h1, A2t; preset gh1 in place
        for (int i = gt; i < NBH; i += NT) {
            int n = i >> 10, j = i & 1023;
            int b = n * G3H + j;
            float r = sigp(g_gi1[b] + g_gh1[b]);
            float z = sigp(g_gi1[b + HDIM] + g_gh1[b + HDIM]);
            float nn = tanhf(g_gi1[b + 2 * HDIM] + r * g_gh1[b + 2 * HDIM]);
            float h = (1.f - z) * nn + z * g_h1f[i];
            g_h1f[i] = h;
            bf16 hb = __float2bfloat16(h);
            g_qb[(8 + (j >> 7)) * CHA + n * AROW + (j & 127)] = hb;
            g_A2t[((size_t)(j >> 6) * NROW + step * NB + n) * FROW + (j & 63)] = hb;
            g_gh1[b] = bhh1[j];
            g_gh1[b + HDIM] = bhh1[j + HDIM];
            g_gh1[b + 2 * HDIM] = bhh1[j + 2 * HDIM];
        }
        gsync(nbk);
    }
}

// ---------------- init ----------------
__global__ void k_init(const float* __restrict__ Wa_b,
                       const float* __restrict__ bhh0, const float* __restrict__ bhh1,
                       const float* __restrict__ bih0, const float* __restrict__ bih1) {
    int i0 = blockIdx.x * 256 + threadIdx.x;
    int st = gridDim.x * 256;
    if (i0 == 0) { g_bar = 0; g_gen = 0; }
    bf16 z = __float2bfloat16(0.f);
    for (int i = i0; i < NBH; i += st) {
        g_h0f[i] = 0.f; g_h1f[i] = 0.f;
        g_Wq[i] = Wa_b[i & 1023];
    }
    for (int i = i0; i < 16 * CHA; i += st) g_qb[i] = z;
    for (int i = i0; i < 8 * CHA; i += st) g_h0b[i] = z;
    for (int i = i0; i < NBG; i += st) {
        int j = i % G3H;
        g_gh0[i] = bhh0[j]; g_gh1[i] = bhh1[j];
        g_gi0[i] = bih0[j]; g_gi1[i] = bih1[j];
    }
}

// ---------------- weight conversion ----------------
__global__ void k_cvtw(const float* __restrict__ wa, const float* __restrict__ hh0,
                       const float* __restrict__ hh1, const float* __restrict__ ih0,
                       const float* __restrict__ ih1, const float* __restrict__ fcw) {
    long st = (long)gridDim.x * blockDim.x;
    long i0 = (long)blockIdx.x * blockDim.x + threadIdx.x;
    for (long i = i0; i < (long)HDIM * XDIM; i += st) {
        int j = (int)(i >> 11), k = (int)(i & 2047);
        g_wWa[(size_t)((j >> 6) * 16 + (k >> 7)) * CHW + (j & 63) * AROW + (k & 127)] =
            __float2bfloat16(wa[i]);
    }
    for (long i = i0; i < (long)G3H * HDIM; i += st) {
        int j = (int)(i >> 10), k = (int)(i & 1023);
        size_t o = (size_t)((j >> 6) * 8 + (k >> 7)) * CHW + (j & 63) * AROW + (k & 127);
        g_wHh0[o] = __float2bfloat16(hh0[i]);
        g_wHh1[o] = __float2bfloat16(hh1[i]);
        g_wIh1[o] = __float2bfloat16(ih1[i]);
    }
    for (long i = i0; i < (long)G3H * XDIM; i += st) {
        int j = (int)(i >> 11), k = (int)(i & 2047);
        g_wIh0[(size_t)((j >> 6) * 16 + (k >> 7)) * CHW + (j & 63) * AROW + (k & 127)] =
            __float2bfloat16(ih0[i]);
    }
    for (long i = i0; i < (long)VOCAB * HDIM; i += st) {
        int v = (int)(i >> 10), k = (int)(i & 1023);
        g_fcwt[((size_t)(k >> 6) * VOCAB + v) * FROW + (k & 63)] = __float2bfloat16(fcw[i]);
    }
}

// ---------------- Uk = keys @ Ua_w^T + Ua_b (tf32 mma, once) ----------------
__global__ void __launch_bounds__(256) k_uk(const float* __restrict__ enc,
                                            const float* __restrict__ Uw,
                                            const float* __restrict__ Ub) {
    __shared__ float sm[2 * UBUF];
    const int bm = blockIdx.y, bn = blockIdx.x;
    const int tid = threadIdx.x;
    const int lane = tid & 31, wid = tid >> 5;
    const int warpM = wid & 1, warpN = wid >> 1;
    const int g = lane >> 2, tg = lane & 3;
    const int am = tid >> 3, ak = (tid & 7) << 2;

    int r = bm * 32 + am;
    const float* Arow = enc + ((size_t)(r & 127) * NB + (r >> 7)) * EHDIM;

    float acc[2][4];
#pragma unroll
    for (int h = 0; h < 2; h++)
#pragma unroll
        for (int u = 0; u < 4; u++) acc[h][u] = 0.f;

    uint sb = (uint)__cvta_generic_to_shared(sm);

#define UISSUE(c) do { \
    uint _b = sb + (uint)(((c) & 1) * UBUF) * 4; \
    int _ko = (c) * 32; \
    cpa16(_b + (uint)(am * 36 + ak) * 4, Arow + _ko + ak); \
    _Pragma("unroll") \
    for (int _i = 0; _i < 2; _i++) { \
        int _idx = tid + _i * 256; \
        int _wn = _idx >> 3, _wk = (_idx & 7) << 2; \
        cpa16(_b + (uint)(32 * 36 + _wn * 36 + _wk) * 4, \
              Uw + (size_t)(bn * 64 + _wn) * EHDIM + _ko + _wk); \
    } } while (0)

    UISSUE(0); CP_COMMIT;
    for (int c = 0; c < 32; ++c) {
        if (c + 1 < 32) { UISSUE(c + 1); CP_COMMIT; CP_WAIT1; }
        else { CP_WAIT0; }
        __syncthreads();
        const float* bA = sm + (c & 1) * UBUF;
        const float* bW = bA + 32 * 36;
        int ar = (warpM * 16 + g) * 36;
        int br = (warpN * 16 + g) * 36;
#pragma unroll
        for (int kk = 0; kk < 4; kk++) {
            int ko = kk * 8 + tg;
            float a0 = bA[ar + ko],       a1 = bA[ar + 288 + ko];
            float a2 = bA[ar + ko + 4],   a3 = bA[ar + 288 + ko + 4];
            float b0 = bW[br + ko],       b1 = bW[br + ko + 4];
            float b2 = bW[br + 288 + ko], b3 = bW[br + 288 + ko + 4];
            mma_tf32(acc[0], a0, a1, a2, a3, b0, b1);
            mma_tf32(acc[1], a0, a1, a2, a3, b2, b3);
        }
        __syncthreads();
    }
#undef UISSUE

    int m = bm * 32 + warpM * 16 + g;
#pragma unroll
    for (int h = 0; h < 2; h++) {
        int j = bn * 64 + warpN * 16 + h * 8 + tg * 2;
        float bb0 = Ub[j], bb1 = Ub[j + 1];
        g_Uk[(size_t)m * HDIM + j]           = acc[h][0] + bb0;
        g_Uk[(size_t)m * HDIM + j + 1]       = acc[h][1] + bb1;
        g_Uk[(size_t)(m + 8) * HDIM + j]     = acc[h][2] + bb0;
        g_Uk[(size_t)(m + 8) * HDIM + j + 1] = acc[h][3] + bb1;
    }
}

// ---------------- FC: 128x128 bf16 tiles; bm fast-varying for fcw reuse ----------------
__global__ void __launch_bounds__(256, 2) k_fc(const float* __restrict__ fcb,
                                               float* __restrict__ out) {
    extern __shared__ char dynsm[];
    int bm = blockIdx.x, bn = blockIdx.y;
    int tid = threadIdx.x, wid = tid >> 5, lane = tid & 31;
    int g = lane >> 2, tg = lane & 3;
    int warpM = wid >> 2, warpN = wid & 3;
    uint sb = (uint)__cvta_generic_to_shared(dynsm);
    uint mb = sb + FBAR_OFF;
    int ph[2] = {0, 0};

    if (tid == 0) { mbar_init(mb, 1); mbar_init(mb + 8, 1); }
    fence_proxy();
    __syncthreads();

    float acc[4][4][4];
#pragma unroll
    for (int a = 0; a < 4; a++)
#pragma unroll
        for (int b = 0; b < 4; b++)
#pragma unroll
            for (int c = 0; c < 4; c++) acc[a][b][c] = 0.f;

    const bf16* Ag = g_A2t + (size_t)bm * 128 * FROW;
    const bf16* Bg = g_fcwt + (size_t)bn * 128 * FROW;

#define FISSUE(kt) do { \
    int _s = (kt) & 1; uint _mbar = mb + _s * 8; \
    if (tid == 0) { \
        mbar_expect(_mbar, FSTAGE_B); \
        uint _dst = sb + _s * FSTAGE_B; \
        bulk_g2s(_dst, Ag + (size_t)(kt) * (NROW * FROW), 128 * 144, _mbar); \
        bulk_g2s(_dst + 128 * 144, Bg + (size_t)(kt) * ((size_t)VOCAB * FROW), 128 * 144, _mbar); \
    } } while (0)

    FISSUE(0);
    for (int kt = 0; kt < 16; kt++) {
        if (kt + 1 < 16) FISSUE(kt + 1);
        int s = kt & 1;
        mbar_wait(mb + s * 8, (uint)ph[s]);
        ph[s] ^= 1;
        const bf16* As = (const bf16*)(dynsm + s * FSTAGE_B);
        const bf16* Bs = As + 128 * FROW;
#pragma unroll
        for (int ks = 0; ks < 4; ks++) {
            int k0 = ks * 16 + tg * 2;
            uint af[4][4], bf[4][2];
#pragma unroll
            for (int mt = 0; mt < 4; mt++) {
                int mrow = warpM * 64 + mt * 16 + g;
                af[mt][0] = *(const uint*)&As[mrow * FROW + k0];
                af[mt][1] = *(const uint*)&As[(mrow + 8) * FROW + k0];
                af[mt][2] = *(const uint*)&As[mrow * FROW + k0 + 8];
                af[mt][3] = *(const uint*)&As[(mrow + 8) * FROW + k0 + 8];
            }
#pragma unroll
            for (int nt = 0; nt < 4; nt++) {
                int nrow = warpN * 32 + nt * 8 + g;
                bf[nt][0] = *(const uint*)&Bs[nrow * FROW + k0];
                bf[nt][1] = *(const uint*)&Bs[nrow * FROW + k0 + 8];
            }
#pragma unroll
            for (int mt = 0; mt < 4; mt++)
#pragma unroll
                for (int nt = 0; nt < 4; nt++)
                    mma_bf16(acc[mt][nt], af[mt][0], af[mt][1], af[mt][2], af[mt][3],
                             bf[nt][0], bf[nt][1]);
        }
        __syncthreads();
    }
#undef FISSUE

#pragma unroll
    for (int mt = 0; mt < 4; mt++) {
#pragma unroll
        for (int nt = 0; nt < 4; nt++) {
            int r0 = bm * 128 + warpM * 64 + mt * 16 + g;
            int c = bn * 128 + warpN * 32 + nt * 8 + tg * 2;
            float bv0 = fcb[c], bv1 = fcb[c + 1];
            {
                int l = r0 >> 5, n = r0 & 31;
                float* p = out + ((size_t)(n * LSEQ + l)) * VOCAB + c;
                p[0] = acc[mt][nt][0] + bv0;
                p[1] = acc[mt][nt][1] + bv1;
            }
            {
                int r1 = r0 + 8;
                int l = r1 >> 5, n = r1 & 31;
                float* p = out + ((size_t)(n * LSEQ + l)) * VOCAB + c;
                p[0] = acc[mt][nt][2] + bv0;
                p[1] = acc[mt][nt][3] + bv1;
            }
        }
    }
}

// ---------------- log_softmax ----------------
__global__ void k_logsoftmax(float* __restrict__ out) {
    __shared__ float rm[256], rs[256];
    int row = blockIdx.x;
    float* p = out + (size_t)row * VOCAB;
    int t = threadIdx.x;
    float m = -1e30f, s = 0.f;
    for (int i = t; i < VOCAB; i += 256) {
        float v = p[i];
        if (v > m) { s = s * __expf(m - v) + 1.f; m = v; }
        else s += __expf(v - m);
    }
    rm[t] = m; rs[t] = s; __syncthreads();
    for (int o = 128; o > 0; o >>= 1) {
        if (t < o) {
            float m2 = rm[t + o], s2 = rs[t + o];
            float M = fmaxf(rm[t], m2);
            rs[t] = rs[t] * __expf(rm[t] - M) + s2 * __expf(m2 - M);
            rm[t] = M;
        }
        __syncthreads();
    }
    float lse = rm[0] + logf(rs[0]);
    for (int i = t; i < VOCAB; i += 256) p[i] -= lse;
}

// ---------------- launch ----------------
extern "C" void kernel_launch(void* const* d_in, const int* in_sizes, int n_in,
                              void* d_out, int out_size) {
    (void)in_sizes; (void)n_in; (void)out_size;
    const float* enc   = (const float*)d_in[0];
    const int*   tgt   = (const int*)  d_in[1];
    const float* emb   = (const float*)d_in[2];
    const float* Wa_w  = (const float*)d_in[3];
    const float* Wa_b  = (const float*)d_in[4];
    const float* Ua_w  = (const float*)d_in[5];
    const float* Ua_b  = (const float*)d_in[6];
    const float* Va_w  = (const float*)d_in[7];
    const float* Va_b  = (const float*)d_in[8];
    const float* W_ih0 = (const float*)d_in[9];
    const float* W_hh0 = (const float*)d_in[10];
    const float* b_ih0 = (const float*)d_in[11];
    const float* b_hh0 = (const float*)d_in[12];
    const float* W_ih1 = (const float*)d_in[13];
    const float* W_hh1 = (const float*)d_in[14];
    const float* b_ih1 = (const float*)d_in[15];
    const float* b_hh1 = (const float*)d_in[16];
    const float* fc_w  = (const float*)d_in[17];
    const float* fc_b  = (const float*)d_in[18];

    float* out = (float*)d_out;
    float* att = out + (size_t)NB * LSEQ * VOCAB;

    static int grid_mega = 0;
    if (grid_mega == 0) {
        cudaFuncSetAttribute(k_mega, cudaFuncAttributeMaxDynamicSharedMemorySize, SMEM_MEGA);
        cudaFuncSetAttribute(k_fc,   cudaFuncAttributeMaxDynamicSharedMemorySize, SMEM_FC);
        int dev = 0;
        cudaGetDevice(&dev);
        cudaDeviceProp prop;
        cudaGetDeviceProperties(&prop, dev);
        int perSM = 1;
        cudaOccupancyMaxActiveBlocksPerMultiprocessor(&perSM, k_mega, 256, SMEM_MEGA);
        if (perSM < 1) perSM = 1;
        if (perSM > 2) perSM = 2;
        grid_mega = prop.multiProcessorCount * perSM;
    }

    k_init<<<256, 256>>>(Wa_b, b_hh0, b_hh1, b_ih0, b_ih1);
    k_cvtw<<<2048, 256>>>(Wa_w, W_hh0, W_hh1, W_ih0, W_ih1, fc_w);
    k_uk<<<dim3(16, 128), 256>>>(enc, Ua_w, Ua_b);
    k_mega<<<grid_mega, 256, SMEM_MEGA>>>(enc, tgt, emb, Wa_b, Va_w, Va_b,
                                          b_ih0, b_hh0, b_ih1, b_hh1, att);
    k_fc<<<dim3(NROW / 128, VOCAB / 128), 256, SMEM_FC>>>(fc_b, out);
    k_logsoftmax<<<NROW, 256>>>(out);
}